// round 2
// baseline (speedup 1.0000x reference)
#include <cuda_runtime.h>
#include <math.h>

// Problem dims
#define L_   2
#define B_   2
#define S_   1024
#define D_   2048
#define H_   16
#define HD_  128
#define SKV_ 1024
#define V_   16384
#define KV2_ 2048          // 2*SKV
#define D3_  6144          // 3*D
#define D4_  8192          // 4*D

// -------- scratch (device globals: allocation-free) --------
__device__ float g_x  [B_*S_*D_];                 // running activations (holds residual)
__device__ float g_xn [B_*S_*D_];                 // layernorm output
__device__ float g_qkv[B_*S_*D3_];                // qkv projection
__device__ float g_q  [B_*H_*S_*HD_];             // gathered Q
__device__ float g_k  [B_*H_*KV2_*HD_];           // assembled K (res ++ patched off)
__device__ float g_v  [B_*H_*KV2_*HD_];           // assembled V
__device__ float g_attn[B_*H_*S_*KV2_];           // attention logits / probs (268MB)
__device__ float g_h  [B_*S_*D4_];                // FFN hidden

// ---------------- helpers ----------------
__device__ __forceinline__ float warpSum(float v) {
    #pragma unroll
    for (int o = 16; o > 0; o >>= 1) v += __shfl_down_sync(0xffffffffu, v, o);
    return v;
}
__device__ __forceinline__ float warpMax(float v) {
    #pragma unroll
    for (int o = 16; o > 0; o >>= 1) v = fmaxf(v, __shfl_down_sync(0xffffffffu, v, o));
    return v;
}
__device__ __forceinline__ float gelu_exact(float x) {
    return 0.5f * x * (1.0f + erff(x * 0.70710678118654752f));
}

// ---------------- positional encoding ----------------
__global__ void pos_enc_kernel(const float* __restrict__ xin,
                               const int* __restrict__ cpos,
                               float* __restrict__ xout) {
    int idx = blockIdx.x * blockDim.x + threadIdx.x;
    if (idx >= B_ * S_ * D_) return;
    int d = idx % D_;
    int s = (idx / D_) % S_;
    int i = d >> 1;
    float freq = expf(-(logf(10000.0f) / (float)D_) * (2.0f * (float)i));
    float ang  = (float)(cpos[0] + s) * freq;
    float pe   = (d & 1) ? cosf(ang) : sinf(ang);
    xout[idx] = xin[idx] + pe;
}

// ---------------- layernorm (row = B*S, width D=2048, 256 thr) ----------------
__global__ __launch_bounds__(256) void layernorm_kernel(
    const float* __restrict__ x, const float* __restrict__ w,
    const float* __restrict__ b, float* __restrict__ out) {
    int row = blockIdx.x;
    const float* p = x + (long)row * D_;
    int tid = threadIdx.x;
    float vals[8];
    float sum = 0.f, sq = 0.f;
    #pragma unroll
    for (int k = 0; k < 8; ++k) {
        float v = p[tid + k * 256];
        vals[k] = v; sum += v; sq += v * v;
    }
    sum = warpSum(sum); sq = warpSum(sq);
    __shared__ float sh_s[8], sh_q[8];
    __shared__ float sh_mean, sh_inv;
    int wid = tid >> 5, lane = tid & 31;
    if (lane == 0) { sh_s[wid] = sum; sh_q[wid] = sq; }
    __syncthreads();
    if (tid == 0) {
        float ts = 0.f, tq = 0.f;
        #pragma unroll
        for (int k = 0; k < 8; ++k) { ts += sh_s[k]; tq += sh_q[k]; }
        float mean = ts / (float)D_;
        float var  = tq / (float)D_ - mean * mean;
        sh_mean = mean;
        sh_inv  = rsqrtf(var + 1e-5f);
    }
    __syncthreads();
    float mean = sh_mean, inv = sh_inv;
    float* o = out + (long)row * D_;
    #pragma unroll
    for (int k = 0; k < 8; ++k) {
        int c = tid + k * 256;
        o[c] = (vals[k] - mean) * inv * w[c] + b[c];
    }
}

// ---------------- gather Q from qkv ----------------
__global__ void gather_q_kernel(float* __restrict__ q) {
    int idx = blockIdx.x * blockDim.x + threadIdx.x;
    if (idx >= B_ * H_ * S_ * HD_) return;
    int d = idx % HD_;
    int s = (idx / HD_) % S_;
    int h = (idx / (HD_ * S_)) % H_;
    int b = idx / (HD_ * S_ * H_);
    q[idx] = g_qkv[(long)(b * S_ + s) * D3_ + h * (3 * HD_) + d];
}

// ---------------- assemble K or V: [res ; off with last slot = new token] ----------------
__global__ void gather_kv_kernel(const float* __restrict__ res,
                                 const float* __restrict__ off,
                                 int layer, int qkv_base,
                                 float* __restrict__ out) {
    int idx = blockIdx.x * blockDim.x + threadIdx.x;
    if (idx >= B_ * H_ * KV2_ * HD_) return;
    int d = idx % HD_;
    int j = (idx / HD_) % KV2_;
    int h = (idx / (HD_ * KV2_)) % H_;
    int b = idx / (HD_ * KV2_ * H_);
    float v;
    if (j < SKV_) {
        v = res[((((long)layer * B_ + b) * H_ + h) * SKV_ + j) * HD_ + d];
    } else {
        int j2 = j - SKV_;
        if (j2 == SKV_ - 1) {
            // new token's k/v from current qkv projection (query position S-1)
            v = g_qkv[(long)(b * S_ + (S_ - 1)) * D3_ + h * (3 * HD_) + qkv_base + d];
        } else {
            v = off[((((long)layer * B_ + b) * H_ + h) * SKV_ + j2) * HD_ + d];
        }
    }
    out[idx] = v;
}

// ---------------- generic batched GEMM:  C = alpha * A @ B^T (+epilogue) ----------------
// A: [M,K] K-major (lda=K). B: if !BNM, rows [N,K] K-major with split pointer
// (row n < nsplit -> B0, else B1); if BNM, B is [K,N] N-major (ldb=N).
// C batch offset = (bz/Hc)*sCb + (bz%Hc)*sCh  (2-level, for scattering heads into x).
// EPI: 0=store, 1=gelu, 2=accumulate into C (residual add).
template<int EPI, bool BNM>
__global__ __launch_bounds__(256) void gemm_tn(
    const float* __restrict__ A, long sAb,
    const float* __restrict__ B0, const float* __restrict__ B1, int nsplit, long sBb,
    float* __restrict__ C, long sCb, long sCh, int Hc, int ldc,
    int K, int ldb, float alpha)
{
    __shared__ float As[16][128];
    __shared__ float Bs[16][128];
    const int bz = blockIdx.z;
    const float* Ab  = A  + (long)bz * sAb;
    const float* B0b = B0 + (long)bz * sBb;
    const float* B1b = B1 ? (B1 + (long)bz * sBb) : (const float*)0;
    float* Cb = C + (long)(bz / Hc) * sCb + (long)(bz % Hc) * sCh;

    const int bm = blockIdx.y * 128;
    const int bn = blockIdx.x * 128;
    const int tid = threadIdx.x;
    const int ty = tid >> 4, tx = tid & 15;
    const int lr  = tid >> 2;          // 0..63
    const int lk  = (tid & 3) << 2;    // 0,4,8,12
    const int bkr = tid >> 5;          // 0..7
    const int bnv = (tid & 31) << 2;   // 0..124

    float acc[8][8];
    #pragma unroll
    for (int i = 0; i < 8; ++i)
        #pragma unroll
        for (int j = 0; j < 8; ++j) acc[i][j] = 0.f;

    for (int k0 = 0; k0 < K; k0 += 16) {
        #pragma unroll
        for (int r = 0; r < 2; ++r) {
            int row = lr + r * 64;
            float4 a = *(const float4*)(Ab + (long)(bm + row) * K + (k0 + lk));
            As[lk + 0][row] = a.x; As[lk + 1][row] = a.y;
            As[lk + 2][row] = a.z; As[lk + 3][row] = a.w;
        }
        if (!BNM) {
            #pragma unroll
            for (int r = 0; r < 2; ++r) {
                int nn = lr + r * 64;
                int n  = bn + nn;
                const float* bp = (n < nsplit) ? (B0b + (long)n * ldb)
                                               : (B1b + (long)(n - nsplit) * ldb);
                float4 bv = *(const float4*)(bp + (k0 + lk));
                Bs[lk + 0][nn] = bv.x; Bs[lk + 1][nn] = bv.y;
                Bs[lk + 2][nn] = bv.z; Bs[lk + 3][nn] = bv.w;
            }
        } else {
            #pragma unroll
            for (int r = 0; r < 2; ++r) {
                int kk = bkr + r * 8;
                float4 bv = *(const float4*)(B0b + (long)(k0 + kk) * ldb + (bn + bnv));
                *(float4*)&Bs[kk][bnv] = bv;
            }
        }
        __syncthreads();
        #pragma unroll
        for (int kk = 0; kk < 16; ++kk) {
            float4 a0 = *(const float4*)&As[kk][ty * 8];
            float4 a1 = *(const float4*)&As[kk][ty * 8 + 4];
            float4 b0 = *(const float4*)&Bs[kk][tx * 8];
            float4 b1 = *(const float4*)&Bs[kk][tx * 8 + 4];
            float ra[8] = {a0.x, a0.y, a0.z, a0.w, a1.x, a1.y, a1.z, a1.w};
            float rb[8] = {b0.x, b0.y, b0.z, b0.w, b1.x, b1.y, b1.z, b1.w};
            #pragma unroll
            for (int i = 0; i < 8; ++i)
                #pragma unroll
                for (int j = 0; j < 8; ++j)
                    acc[i][j] = fmaf(ra[i], rb[j], acc[i][j]);
        }
        __syncthreads();
    }
    #pragma unroll
    for (int i = 0; i < 8; ++i) {
        long row = bm + ty * 8 + i;
        #pragma unroll
        for (int j = 0; j < 8; ++j) {
            long col = bn + tx * 8 + j;
            float v = acc[i][j] * alpha;
            float* cp = Cb + row * (long)ldc + col;
            if (EPI == 1) v = gelu_exact(v);
            if (EPI == 2) v += *cp;
            *cp = v;
        }
    }
}

// ---------------- row softmax (streaming, in-place), 256 thr/row ----------------
__global__ __launch_bounds__(256) void softmax_rows(float* __restrict__ data, int width) {
    long row = blockIdx.x;
    float* p = data + row * (long)width;
    int tid = threadIdx.x;
    int wid = tid >> 5, lane = tid & 31;
    __shared__ float sh[8];
    __shared__ float sh_bcast;

    float m = -3.0e38f;
    for (int c = tid; c < width; c += 256) m = fmaxf(m, p[c]);
    m = warpMax(m);
    if (lane == 0) sh[wid] = m;
    __syncthreads();
    if (tid == 0) {
        float t = sh[0];
        #pragma unroll
        for (int k = 1; k < 8; ++k) t = fmaxf(t, sh[k]);
        sh_bcast = t;
    }
    __syncthreads();
    m = sh_bcast;

    float s = 0.f;
    for (int c = tid; c < width; c += 256) {
        float e = expf(p[c] - m);
        p[c] = e;
        s += e;
    }
    s = warpSum(s);
    if (lane == 0) sh[wid] = s;
    __syncthreads();
    if (tid == 0) {
        float t = 0.f;
        #pragma unroll
        for (int k = 0; k < 8; ++k) t += sh[k];
        sh_bcast = t;
    }
    __syncthreads();
    float inv = 1.0f / sh_bcast;
    for (int c = tid; c < width; c += 256) p[c] *= inv;
}

// ---------------- host orchestration ----------------
extern "C" void kernel_launch(void* const* d_in, const int* in_sizes, int n_in,
                              void* d_out, int out_size) {
    const float* x_in   = (const float*)d_in[0];
    const float* ln_w   = (const float*)d_in[1];
    const float* ln_b   = (const float*)d_in[2];
    const float* qkv_r  = (const float*)d_in[3];
    const float* qkv_o  = (const float*)d_in[4];
    const float* k_res  = (const float*)d_in[5];
    const float* v_res  = (const float*)d_in[6];
    const float* k_off  = (const float*)d_in[7];
    const float* v_off  = (const float*)d_in[8];
    const float* f1_r   = (const float*)d_in[9];
    const float* f1_o   = (const float*)d_in[10];
    const float* f2_r   = (const float*)d_in[11];
    const float* f2_o   = (const float*)d_in[12];
    const float* o_res  = (const float*)d_in[13];
    const float* o_off  = (const float*)d_in[14];
    const int*   cpos   = (const int*)d_in[15];
    float* out = (float*)d_out;

    float *px, *pxn, *pqkv, *pq, *pk, *pv, *pattn, *ph;
    cudaGetSymbolAddress((void**)&px,    g_x);
    cudaGetSymbolAddress((void**)&pxn,   g_xn);
    cudaGetSymbolAddress((void**)&pqkv,  g_qkv);
    cudaGetSymbolAddress((void**)&pq,    g_q);
    cudaGetSymbolAddress((void**)&pk,    g_k);
    cudaGetSymbolAddress((void**)&pv,    g_v);
    cudaGetSymbolAddress((void**)&pattn, g_attn);
    cudaGetSymbolAddress((void**)&ph,    g_h);

    const int   NOSPLIT = 0x7fffffff;
    const float attn_scale = 0.08838834764831845f;  // 1/sqrt(128)
    const int   M = B_ * S_;                        // 2048

    // x = x_in + PE
    pos_enc_kernel<<<(B_ * S_ * D_ + 255) / 256, 256>>>(x_in, cpos, px);

    for (int i = 0; i < L_; ++i) {
        // ---- attention block ----
        layernorm_kernel<<<M, 256>>>(px, ln_w, ln_b, pxn);

        // qkv = xn @ [qkv_res[i]; qkv_off[i]]^T   [2048 x 6144]
        gemm_tn<0, false><<<dim3(D3_ / 128, M / 128, 1), 256>>>(
            pxn, 0, qkv_r + (long)i * (D3_ / 2) * D_, qkv_o + (long)i * (D3_ / 2) * D_,
            D3_ / 2, 0, pqkv, 0, 0, 1, D3_, D_, D_, 1.0f);

        gather_q_kernel<<<(B_ * H_ * S_ * HD_ + 255) / 256, 256>>>(pq);
        gather_kv_kernel<<<(B_ * H_ * KV2_ * HD_ + 255) / 256, 256>>>(k_res, k_off, i, HD_, pk);
        gather_kv_kernel<<<(B_ * H_ * KV2_ * HD_ + 255) / 256, 256>>>(v_res, v_off, i, 2 * HD_, pv);

        // logits = scale * Q @ K^T  (batched over 32 (b,h); M=1024, N=2048, K=128)
        gemm_tn<0, false><<<dim3(KV2_ / 128, S_ / 128, B_ * H_), 256>>>(
            pq, (long)S_ * HD_, pk, (const float*)0, NOSPLIT, (long)KV2_ * HD_,
            pattn, (long)S_ * KV2_, 0, 1, KV2_, HD_, HD_, attn_scale);

        softmax_rows<<<B_ * H_ * S_, 256>>>(pattn, KV2_);

        // x += P @ V  (batched; scatter each head's 128 cols into x at h*HD)
        gemm_tn<2, true><<<dim3(HD_ / 128, S_ / 128, B_ * H_), 256>>>(
            pattn, (long)S_ * KV2_, pv, (const float*)0, NOSPLIT, (long)KV2_ * HD_,
            px, (long)S_ * D_, HD_, H_, D_, KV2_, HD_, 1.0f);

        // ---- FFN block ----
        layernorm_kernel<<<M, 256>>>(px, ln_w, ln_b, pxn);

        // h = gelu(xn @ [ffn1_res[i]; ffn1_off[i]]^T)   [2048 x 8192]
        gemm_tn<1, false><<<dim3(D4_ / 128, M / 128, 1), 256>>>(
            pxn, 0, f1_r + (long)i * (D4_ / 2) * D_, f1_o + (long)i * (D4_ / 2) * D_,
            D4_ / 2, 0, ph, 0, 0, 1, D4_, D_, D_, 1.0f);

        // x += h @ [ffn2_res[i]; ffn2_off[i]]^T   [2048 x 2048], K=8192
        gemm_tn<2, false><<<dim3(D_ / 128, M / 128, 1), 256>>>(
            ph, 0, f2_r + (long)i * (D_ / 2) * D4_, f2_o + (long)i * (D_ / 2) * D4_,
            D_ / 2, 0, px, 0, 0, 1, D_, D4_, D4_, 1.0f);
    }

    // final LN + output projection + softmax
    layernorm_kernel<<<M, 256>>>(px, ln_w, ln_b, pxn);
    gemm_tn<0, false><<<dim3(V_ / 128, M / 128, 1), 256>>>(
        pxn, 0, o_res, o_off, V_ / 2, 0, out, 0, 0, 1, V_, D_, D_, 1.0f);
    softmax_rows<<<M, 256>>>(out, V_);
}

// round 8
// speedup vs baseline: 2.3065x; 2.3065x over previous
#include <cuda_runtime.h>
#include <cuda_bf16.h>
#include <math.h>
#include <stdint.h>

#define L_   2
#define B_   2
#define S_   1024
#define D_   2048
#define H_   16
#define HD_  128
#define SKV_ 1024
#define V_   16384
#define KV2_ 2048
#define D3_  6144
#define D4_  8192
#define BS_  (B_*S_)

typedef __nv_bfloat16 bf16;

// ---------------- device scratch (allocation-free) ----------------
__device__ float g_x   [BS_*D_];
__device__ float g_qkv [BS_*D3_];
__device__ float g_logit[B_*H_*S_*KV2_];
__device__ __align__(16) bf16  g_xn_hi[BS_*D_],      g_xn_lo[BS_*D_];
__device__ __align__(16) bf16  g_q_hi [B_*H_*S_*HD_],   g_q_lo [B_*H_*S_*HD_];
__device__ __align__(16) bf16  g_k_hi [B_*H_*KV2_*HD_], g_k_lo [B_*H_*KV2_*HD_];
__device__ __align__(16) bf16  g_vt_hi[B_*H_*HD_*KV2_], g_vt_lo[B_*H_*HD_*KV2_];
__device__ __align__(16) bf16  g_p_hi [B_*H_*S_*KV2_],  g_p_lo [B_*H_*S_*KV2_];
__device__ __align__(16) bf16  g_h_hi [BS_*D4_],     g_h_lo [BS_*D4_];
__device__ __align__(16) bf16 w_qr_hi[L_*(D3_/2)*D_], w_qr_lo[L_*(D3_/2)*D_];
__device__ __align__(16) bf16 w_qo_hi[L_*(D3_/2)*D_], w_qo_lo[L_*(D3_/2)*D_];
__device__ __align__(16) bf16 w_1r_hi[L_*(D4_/2)*D_], w_1r_lo[L_*(D4_/2)*D_];
__device__ __align__(16) bf16 w_1o_hi[L_*(D4_/2)*D_], w_1o_lo[L_*(D4_/2)*D_];
__device__ __align__(16) bf16 w_2r_hi[L_*(D_/2)*D4_], w_2r_lo[L_*(D_/2)*D4_];
__device__ __align__(16) bf16 w_2o_hi[L_*(D_/2)*D4_], w_2o_lo[L_*(D_/2)*D4_];
__device__ __align__(16) bf16 w_or_hi[(V_/2)*D_],     w_or_lo[(V_/2)*D_];
__device__ __align__(16) bf16 w_oo_hi[(V_/2)*D_],     w_oo_lo[(V_/2)*D_];

// ---------------- helpers ----------------
__device__ __forceinline__ uint32_t smem_u32(const void* p) {
    uint32_t a;
    asm("{ .reg .u64 t; cvta.to.shared.u64 t, %1; cvt.u32.u64 %0, t; }" : "=r"(a) : "l"(p));
    return a;
}
__device__ __forceinline__ void cp16(uint32_t d, const void* g) {
    asm volatile("cp.async.cg.shared.global [%0], [%1], 16;" :: "r"(d), "l"(g));
}
#define CP_COMMIT() asm volatile("cp.async.commit_group;" ::: "memory")

#define LDX4(r, a) \
    asm volatile("ldmatrix.sync.aligned.m8n8.x4.shared.b16 {%0,%1,%2,%3}, [%4];" \
        : "=r"((r)[0]), "=r"((r)[1]), "=r"((r)[2]), "=r"((r)[3]) : "r"(a))
#define LDX2(r, a) \
    asm volatile("ldmatrix.sync.aligned.m8n8.x2.shared.b16 {%0,%1}, [%2];" \
        : "=r"((r)[0]), "=r"((r)[1]) : "r"(a))
#define MMA_BF16(c, a, b) \
    asm volatile("mma.sync.aligned.m16n8k16.row.col.f32.bf16.bf16.f32 " \
        "{%0,%1,%2,%3}, {%4,%5,%6,%7}, {%8,%9}, {%0,%1,%2,%3};" \
        : "+f"((c)[0]), "+f"((c)[1]), "+f"((c)[2]), "+f"((c)[3]) \
        : "r"((a)[0]), "r"((a)[1]), "r"((a)[2]), "r"((a)[3]), "r"((b)[0]), "r"((b)[1]))

__device__ __forceinline__ void split_store(float v, bf16* hp, bf16* lp) {
    bf16 h = __float2bfloat16(v);
    *hp = h;
    *lp = __float2bfloat16(v - __bfloat162float(h));
}
__device__ __forceinline__ float gelu_exact(float x) {
    return 0.5f * x * (1.0f + erff(x * 0.70710678118654752f));
}
__device__ __forceinline__ float warpSum(float v) {
    #pragma unroll
    for (int o = 16; o > 0; o >>= 1) v += __shfl_down_sync(0xffffffffu, v, o);
    return v;
}
__device__ __forceinline__ float warpMax(float v) {
    #pragma unroll
    for (int o = 16; o > 0; o >>= 1) v = fmaxf(v, __shfl_down_sync(0xffffffffu, v, o));
    return v;
}

// ================= mma.sync bf16x3 GEMM =================
// C[M,N] = alpha * A @ B^T ; fp32-equivalent via hh + h*lo + lo*h.
// A: [M,K] K-major hi/lo. B: rows [N,K] K-major hi/lo, split pointer at nsplit.
// CTA 128x128, 256 thr (8 warps 2x4, warp tile 64x32), K-step 32, double buffer.
// SMEM stage: Ah(10240) Al(10240) Bh(10240) Bl(10240); row pitch 80B (conflict-free ldmatrix).
// EPI 0: C=fp32 store*alpha; 1: gelu -> (Chi,Clo); 2: C += acc.
#define STG_     40960u
#define MM_SMEM  (2*40960)

template<int EPI>
__global__ __launch_bounds__(256) void mm3(
    const bf16* __restrict__ Ahi, const bf16* __restrict__ Alo, long sAb, int lda,
    const bf16* __restrict__ B0hi, const bf16* __restrict__ B0lo,
    const bf16* __restrict__ B1hi, const bf16* __restrict__ B1lo,
    int nsplit, long sBb, int ldb,
    float* __restrict__ C, bf16* __restrict__ Chi, bf16* __restrict__ Clo,
    long sCb, long sCh, int Hc, int ldc,
    int K, float alpha)
{
    extern __shared__ __align__(128) char smem[];
    const uint32_t sb = smem_u32(smem);
    const int tid = threadIdx.x;
    const int lid = tid & 31, wid = tid >> 5;
    const int bz = blockIdx.z;
    const int bm = blockIdx.y * 128;
    const int bn = blockIdx.x * 128;

    const bf16* Ahb  = Ahi + (long)bz * sAb + (long)bm * lda;
    const bf16* Alb  = Alo + (long)bz * sAb + (long)bm * lda;
    const bf16* B0hb = B0hi + (long)bz * sBb;
    const bf16* B0lb = B0lo + (long)bz * sBb;
    const bf16* B1hb = B1hi ? (B1hi + (long)bz * sBb) : (const bf16*)0;
    const bf16* B1lb = B1lo ? (B1lo + (long)bz * sBb) : (const bf16*)0;

    // per-thread cp.async assignments: 512 16B-chunks per matrix, 2 per thread
    // chunk i: row = i>>2, sub = i&3
    const int i0r = tid >> 2,        i0c = tid & 3;
    const int i1r = (tid + 256) >> 2, i1c = (tid + 256) & 3;
    // B row pointers (row index fixed per thread across all k)
    const int nA0 = bn + i0r, nA1 = bn + i1r;
    const bf16* bh0 = (nA0 < nsplit) ? (B0hb + (long)nA0 * ldb) : (B1hb + (long)(nA0 - nsplit) * ldb);
    const bf16* bl0 = (nA0 < nsplit) ? (B0lb + (long)nA0 * ldb) : (B1lb + (long)(nA0 - nsplit) * ldb);
    const bf16* bh1 = (nA1 < nsplit) ? (B0hb + (long)nA1 * ldb) : (B1hb + (long)(nA1 - nsplit) * ldb);
    const bf16* bl1 = (nA1 < nsplit) ? (B0lb + (long)nA1 * ldb) : (B1lb + (long)(nA1 - nsplit) * ldb);
    const bf16* ah0 = Ahb + (long)i0r * lda;
    const bf16* al0 = Alb + (long)i0r * lda;
    const bf16* ah1 = Ahb + (long)i1r * lda;
    const bf16* al1 = Alb + (long)i1r * lda;
    const uint32_t dA0 = sb + (uint32_t)i0r * 80 + (uint32_t)i0c * 16;
    const uint32_t dA1 = sb + (uint32_t)i1r * 80 + (uint32_t)i1c * 16;

    // ldmatrix lane offsets
    const int mbase = (wid >> 2) * 64;
    const int nbase = (wid & 3) * 32;
    const uint32_t aoff = (uint32_t)(mbase + (lid & 15)) * 80 + (uint32_t)(lid >> 4) * 16;
    const uint32_t boff = 20480u + (uint32_t)(nbase + (lid & 7)) * 80 + (uint32_t)((lid >> 3) & 1) * 16;

    float acc[4][4][4];
    #pragma unroll
    for (int a = 0; a < 4; ++a)
        #pragma unroll
        for (int b = 0; b < 4; ++b)
            #pragma unroll
            for (int c = 0; c < 4; ++c) acc[a][b][c] = 0.f;

    auto load_stage = [&](int c, int buf) {
        const uint32_t so = (uint32_t)buf * STG_;
        const int k0 = c * 32;
        const int e0 = k0 + i0c * 8, e1 = k0 + i1c * 8;
        cp16(dA0 + so,           ah0 + e0);
        cp16(dA0 + so + 10240u,  al0 + e0);
        cp16(dA1 + so,           ah1 + e1);
        cp16(dA1 + so + 10240u,  al1 + e1);
        cp16(dA0 + so + 20480u,  bh0 + e0);
        cp16(dA0 + so + 30720u,  bl0 + e0);
        cp16(dA1 + so + 20480u,  bh1 + e1);
        cp16(dA1 + so + 30720u,  bl1 + e1);
        CP_COMMIT();
    };

    const int nc = K / 32;
    load_stage(0, 0);

    for (int c = 0; c < nc; ++c) {
        const int buf = c & 1;
        if (c + 1 < nc) {
            load_stage(c + 1, buf ^ 1);
            asm volatile("cp.async.wait_group 1;" ::: "memory");
        } else {
            asm volatile("cp.async.wait_group 0;" ::: "memory");
        }
        __syncthreads();

        const uint32_t sbase = sb + (uint32_t)buf * STG_;
        #pragma unroll
        for (int kk = 0; kk < 2; ++kk) {
            uint32_t bh[4][2], bl[4][2];
            #pragma unroll
            for (int nt = 0; nt < 4; ++nt) {
                uint32_t bd = sbase + boff + (uint32_t)nt * 640 + (uint32_t)kk * 32;
                LDX2(bh[nt], bd);
                LDX2(bl[nt], bd + 10240u);
            }
            #pragma unroll
            for (int mt = 0; mt < 4; ++mt) {
                uint32_t ah[4], al[4];
                uint32_t ad = sbase + aoff + (uint32_t)mt * 1280 + (uint32_t)kk * 32;
                LDX4(ah, ad);
                LDX4(al, ad + 10240u);
                #pragma unroll
                for (int nt = 0; nt < 4; ++nt) {
                    MMA_BF16(acc[mt][nt], ah, bh[nt]);
                    MMA_BF16(acc[mt][nt], ah, bl[nt]);
                    MMA_BF16(acc[mt][nt], al, bh[nt]);
                }
            }
        }
        __syncthreads();
    }

    // ---------------- epilogue ----------------
    const long coff = (long)(bz / Hc) * sCb + (long)(bz % Hc) * sCh;
    #pragma unroll
    for (int mt = 0; mt < 4; ++mt) {
        #pragma unroll
        for (int half = 0; half < 2; ++half) {
            long m = bm + mbase + mt * 16 + (lid >> 2) + half * 8;
            long rbase = coff + m * (long)ldc + bn + nbase + 2 * (lid & 3);
            #pragma unroll
            for (int nt = 0; nt < 4; ++nt) {
                long idx = rbase + nt * 8;
                float v0 = acc[mt][nt][half * 2 + 0] * alpha;
                float v1 = acc[mt][nt][half * 2 + 1] * alpha;
                if (EPI == 0) {
                    C[idx] = v0; C[idx + 1] = v1;
                } else if (EPI == 1) {
                    float gg0 = gelu_exact(v0), gg1 = gelu_exact(v1);
                    split_store(gg0, &Chi[idx], &Clo[idx]);
                    split_store(gg1, &Chi[idx + 1], &Clo[idx + 1]);
                } else {
                    C[idx]     += v0;
                    C[idx + 1] += v1;
                }
            }
        }
    }
}

// ================= elementwise kernels =================
__global__ void cvt_hilo(const float* __restrict__ x, bf16* __restrict__ hi, bf16* __restrict__ lo, int n) {
    int i = blockIdx.x * blockDim.x + threadIdx.x;
    if (i < n) split_store(x[i], &hi[i], &lo[i]);
}

__global__ void pos_enc_kernel(const float* __restrict__ xin, const int* __restrict__ cpos,
                               float* __restrict__ xout) {
    int idx = blockIdx.x * blockDim.x + threadIdx.x;
    if (idx >= B_ * S_ * D_) return;
    int d = idx % D_;
    int s = (idx / D_) % S_;
    int i = d >> 1;
    float freq = expf(-(logf(10000.0f) / (float)D_) * (2.0f * (float)i));
    float ang  = (float)(cpos[0] + s) * freq;
    float pe   = (d & 1) ? cosf(ang) : sinf(ang);
    xout[idx] = xin[idx] + pe;
}

__global__ __launch_bounds__(256) void layernorm_kernel(
    const float* __restrict__ x, const float* __restrict__ w, const float* __restrict__ b,
    bf16* __restrict__ ohi, bf16* __restrict__ olo) {
    int row = blockIdx.x;
    const float* p = x + (long)row * D_;
    int tid = threadIdx.x;
    float vals[8];
    float sum = 0.f, sq = 0.f;
    #pragma unroll
    for (int k = 0; k < 8; ++k) {
        float v = p[tid + k * 256];
        vals[k] = v; sum += v; sq += v * v;
    }
    sum = warpSum(sum); sq = warpSum(sq);
    __shared__ float sh_s[8], sh_q[8];
    __shared__ float sh_mean, sh_inv;
    int wid = tid >> 5, lane = tid & 31;
    if (lane == 0) { sh_s[wid] = sum; sh_q[wid] = sq; }
    __syncthreads();
    if (tid == 0) {
        float ts = 0.f, tq = 0.f;
        #pragma unroll
        for (int k = 0; k < 8; ++k) { ts += sh_s[k]; tq += sh_q[k]; }
        float mean = ts / (float)D_;
        float var  = tq / (float)D_ - mean * mean;
        sh_mean = mean; sh_inv = rsqrtf(var + 1e-5f);
    }
    __syncthreads();
    float mean = sh_mean, inv = sh_inv;
    long base = (long)row * D_;
    #pragma unroll
    for (int k = 0; k < 8; ++k) {
        int c = tid + k * 256;
        float y = (vals[k] - mean) * inv * w[c] + b[c];
        split_store(y, &ohi[base + c], &olo[base + c]);
    }
}

__global__ void gather_q_kernel(bf16* __restrict__ hi, bf16* __restrict__ lo) {
    int idx = blockIdx.x * blockDim.x + threadIdx.x;
    if (idx >= B_ * H_ * S_ * HD_) return;
    int d = idx % HD_;
    int s = (idx / HD_) % S_;
    int h = (idx / (HD_ * S_)) % H_;
    int b = idx / (HD_ * S_ * H_);
    float v = g_qkv[(long)(b * S_ + s) * D3_ + h * (3 * HD_) + d];
    split_store(v, &hi[idx], &lo[idx]);
}

__global__ void gather_k_kernel(const float* __restrict__ res, const float* __restrict__ off,
                                int layer, bf16* __restrict__ hi, bf16* __restrict__ lo) {
    int idx = blockIdx.x * blockDim.x + threadIdx.x;
    if (idx >= B_ * H_ * KV2_ * HD_) return;
    int d = idx % HD_;
    int j = (idx / HD_) % KV2_;
    int h = (idx / (HD_ * KV2_)) % H_;
    int b = idx / (HD_ * KV2_ * H_);
    float v;
    if (j < SKV_) {
        v = res[((((long)layer * B_ + b) * H_ + h) * SKV_ + j) * HD_ + d];
    } else {
        int j2 = j - SKV_;
        if (j2 == SKV_ - 1)
            v = g_qkv[(long)(b * S_ + (S_ - 1)) * D3_ + h * (3 * HD_) + HD_ + d];
        else
            v = off[((((long)layer * B_ + b) * H_ + h) * SKV_ + j2) * HD_ + d];
    }
    split_store(v, &hi[idx], &lo[idx]);
}

__global__ void gather_vt_kernel(const float* __restrict__ res, const float* __restrict__ off,
                                 int layer, bf16* __restrict__ hi, bf16* __restrict__ lo) {
    int idx = blockIdx.x * blockDim.x + threadIdx.x;
    if (idx >= B_ * H_ * HD_ * KV2_) return;
    int j = idx % KV2_;
    int d = (idx / KV2_) % HD_;
    int h = (idx / (KV2_ * HD_)) % H_;
    int b = idx / (KV2_ * HD_ * H_);
    float v;
    if (j < SKV_) {
        v = res[((((long)layer * B_ + b) * H_ + h) * SKV_ + j) * HD_ + d];
    } else {
        int j2 = j - SKV_;
        if (j2 == SKV_ - 1)
            v = g_qkv[(long)(b * S_ + (S_ - 1)) * D3_ + h * (3 * HD_) + 2 * HD_ + d];
        else
            v = off[((((long)layer * B_ + b) * H_ + h) * SKV_ + j2) * HD_ + d];
    }
    split_store(v, &hi[idx], &lo[idx]);
}

__global__ __launch_bounds__(256) void softmax_p(const float* __restrict__ logit,
                                                 bf16* __restrict__ phi, bf16* __restrict__ plo) {
    long row = blockIdx.x;
    const float* p = logit + row * KV2_;
    int tid = threadIdx.x;
    int wid = tid >> 5, lane = tid & 31;
    __shared__ float sh[8];
    __shared__ float sh_b;
    float vals[8];
    float m = -3.0e38f;
    #pragma unroll
    for (int k = 0; k < 8; ++k) { vals[k] = p[tid + k * 256]; m = fmaxf(m, vals[k]); }
    m = warpMax(m);
    if (lane == 0) sh[wid] = m;
    __syncthreads();
    if (tid == 0) {
        float t = sh[0];
        #pragma unroll
        for (int k = 1; k < 8; ++k) t = fmaxf(t, sh[k]);
        sh_b = t;
    }
    __syncthreads();
    m = sh_b;
    float s = 0.f;
    #pragma unroll
    for (int k = 0; k < 8; ++k) { vals[k] = expf(vals[k] - m); s += vals[k]; }
    s = warpSum(s);
    if (lane == 0) sh[wid] = s;
    __syncthreads();
    if (tid == 0) {
        float t = 0.f;
        #pragma unroll
        for (int k = 0; k < 8; ++k) t += sh[k];
        sh_b = t;
    }
    __syncthreads();
    float inv = 1.0f / sh_b;
    long base = row * KV2_;
    #pragma unroll
    for (int k = 0; k < 8; ++k) {
        int c = tid + k * 256;
        split_store(vals[k] * inv, &phi[base + c], &plo[base + c]);
    }
}

__global__ __launch_bounds__(256) void softmax_rows(float* __restrict__ data, int width) {
    long row = blockIdx.x;
    float* p = data + row * (long)width;
    int tid = threadIdx.x;
    int wid = tid >> 5, lane = tid & 31;
    __shared__ float sh[8];
    __shared__ float sh_b;
    float m = -3.0e38f;
    for (int c = tid; c < width; c += 256) m = fmaxf(m, p[c]);
    m = warpMax(m);
    if (lane == 0) sh[wid] = m;
    __syncthreads();
    if (tid == 0) {
        float t = sh[0];
        #pragma unroll
        for (int k = 1; k < 8; ++k) t = fmaxf(t, sh[k]);
        sh_b = t;
    }
    __syncthreads();
    m = sh_b;
    float s = 0.f;
    for (int c = tid; c < width; c += 256) {
        float e = expf(p[c] - m);
        p[c] = e; s += e;
    }
    s = warpSum(s);
    if (lane == 0) sh[wid] = s;
    __syncthreads();
    if (tid == 0) {
        float t = 0.f;
        #pragma unroll
        for (int k = 0; k < 8; ++k) t += sh[k];
        sh_b = t;
    }
    __syncthreads();
    float inv = 1.0f / sh_b;
    for (int c = tid; c < width; c += 256) p[c] *= inv;
}

// ================= host orchestration =================
extern "C" void kernel_launch(void* const* d_in, const int* in_sizes, int n_in,
                              void* d_out, int out_size) {
    const float* x_in  = (const float*)d_in[0];
    const float* ln_w  = (const float*)d_in[1];
    const float* ln_b  = (const float*)d_in[2];
    const float* qkv_r = (const float*)d_in[3];
    const float* qkv_o = (const float*)d_in[4];
    const float* k_res = (const float*)d_in[5];
    const float* v_res = (const float*)d_in[6];
    const float* k_off = (const float*)d_in[7];
    const float* v_off = (const float*)d_in[8];
    const float* f1_r  = (const float*)d_in[9];
    const float* f1_o  = (const float*)d_in[10];
    const float* f2_r  = (const float*)d_in[11];
    const float* f2_o  = (const float*)d_in[12];
    const float* o_res = (const float*)d_in[13];
    const float* o_off = (const float*)d_in[14];
    const int*   cpos  = (const int*)d_in[15];
    float* out = (float*)d_out;

    #define GSA(p, sym) void* p##_v; cudaGetSymbolAddress(&p##_v, sym); auto p = (decltype(&sym[0]))p##_v
    GSA(px, g_x);       GSA(pqkv, g_qkv);   GSA(plog, g_logit);
    GSA(xnh, g_xn_hi);  GSA(xnl, g_xn_lo);
    GSA(qh, g_q_hi);    GSA(ql, g_q_lo);
    GSA(kh, g_k_hi);    GSA(kl, g_k_lo);
    GSA(vth, g_vt_hi);  GSA(vtl, g_vt_lo);
    GSA(pph, g_p_hi);   GSA(ppl, g_p_lo);
    GSA(hh, g_h_hi);    GSA(hl, g_h_lo);
    GSA(qrh, w_qr_hi);  GSA(qrl, w_qr_lo);  GSA(qoh, w_qo_hi);  GSA(qol, w_qo_lo);
    GSA(w1rh, w_1r_hi); GSA(w1rl, w_1r_lo); GSA(w1oh, w_1o_hi); GSA(w1ol, w_1o_lo);
    GSA(w2rh, w_2r_hi); GSA(w2rl, w_2r_lo); GSA(w2oh, w_2o_hi); GSA(w2ol, w_2o_lo);
    GSA(worh, w_or_hi); GSA(worl, w_or_lo); GSA(wooh, w_oo_hi); GSA(wool, w_oo_lo);
    #undef GSA

    cudaFuncSetAttribute(mm3<0>, cudaFuncAttributeMaxDynamicSharedMemorySize, MM_SMEM);
    cudaFuncSetAttribute(mm3<1>, cudaFuncAttributeMaxDynamicSharedMemorySize, MM_SMEM);
    cudaFuncSetAttribute(mm3<2>, cudaFuncAttributeMaxDynamicSharedMemorySize, MM_SMEM);

    const int NOSPLIT = 0x7fffffff;
    const float attn_scale = 0.08838834764831845f;
    const int M = BS_;

    // weight conversion fp32 -> bf16 hi/lo
    const int nQ = L_ * (D3_ / 2) * D_;
    const int n1 = L_ * (D4_ / 2) * D_;
    const int n2 = L_ * (D_ / 2) * D4_;
    const int nO = (V_ / 2) * D_;
    cvt_hilo<<<(nQ + 255) / 256, 256>>>(qkv_r, qrh, qrl, nQ);
    cvt_hilo<<<(nQ + 255) / 256, 256>>>(qkv_o, qoh, qol, nQ);
    cvt_hilo<<<(n1 + 255) / 256, 256>>>(f1_r, w1rh, w1rl, n1);
    cvt_hilo<<<(n1 + 255) / 256, 256>>>(f1_o, w1oh, w1ol, n1);
    cvt_hilo<<<(n2 + 255) / 256, 256>>>(f2_r, w2rh, w2rl, n2);
    cvt_hilo<<<(n2 + 255) / 256, 256>>>(f2_o, w2oh, w2ol, n2);
    cvt_hilo<<<(nO + 255) / 256, 256>>>(o_res, worh, worl, nO);
    cvt_hilo<<<(nO + 255) / 256, 256>>>(o_off, wooh, wool, nO);

    pos_enc_kernel<<<(B_ * S_ * D_ + 255) / 256, 256>>>(x_in, cpos, px);

    for (int i = 0; i < L_; ++i) {
        const long oq = (long)i * (D3_ / 2) * D_;
        const long o1 = (long)i * (D4_ / 2) * D_;
        const long o2 = (long)i * (D_ / 2) * D4_;

        // ---- attention ----
        layernorm_kernel<<<M, 256>>>(px, ln_w, ln_b, xnh, xnl);

        mm3<0><<<dim3(D3_ / 128, M / 128, 1), 256, MM_SMEM>>>(
            xnh, xnl, 0, D_, qrh + oq, qrl + oq, qoh + oq, qol + oq, D3_ / 2, 0, D_,
            pqkv, (bf16*)0, (bf16*)0, 0, 0, 1, D3_, D_, 1.0f);

        gather_q_kernel<<<(B_ * H_ * S_ * HD_ + 255) / 256, 256>>>(qh, ql);
        gather_k_kernel<<<(B_ * H_ * KV2_ * HD_ + 255) / 256, 256>>>(k_res, k_off, i, kh, kl);
        gather_vt_kernel<<<(B_ * H_ * HD_ * KV2_ + 255) / 256, 256>>>(v_res, v_off, i, vth, vtl);

        // logits = scale * Q @ K^T : batch 32, M=1024, N=2048, K=128
        mm3<0><<<dim3(KV2_ / 128, S_ / 128, B_ * H_), 256, MM_SMEM>>>(
            qh, ql, (long)S_ * HD_, HD_, kh, kl, (bf16*)0, (bf16*)0, NOSPLIT,
            (long)KV2_ * HD_, HD_,
            plog, (bf16*)0, (bf16*)0, (long)S_ * KV2_, 0, 1, KV2_, HD_, attn_scale);

        softmax_p<<<B_ * H_ * S_, 256>>>(plog, pph, ppl);

        // x += P @ V : batch 32, M=1024, N=128, K=2048; scatter to head offset
        mm3<2><<<dim3(1, S_ / 128, B_ * H_), 256, MM_SMEM>>>(
            pph, ppl, (long)S_ * KV2_, KV2_, vth, vtl, (bf16*)0, (bf16*)0, NOSPLIT,
            (long)HD_ * KV2_, KV2_,
            px, (bf16*)0, (bf16*)0, (long)S_ * D_, HD_, H_, D_, KV2_, 1.0f);

        // ---- FFN ----
        layernorm_kernel<<<M, 256>>>(px, ln_w, ln_b, xnh, xnl);

        mm3<1><<<dim3(D4_ / 128, M / 128, 1), 256, MM_SMEM>>>(
            xnh, xnl, 0, D_, w1rh + o1, w1rl + o1, w1oh + o1, w1ol + o1, D4_ / 2, 0, D_,
            (float*)0, hh, hl, 0, 0, 1, D4_, D_, 1.0f);

        mm3<2><<<dim3(D_ / 128, M / 128, 1), 256, MM_SMEM>>>(
            hh, hl, 0, D4_, w2rh + o2, w2rl + o2, w2oh + o2, w2ol + o2, D_ / 2, 0, D4_,
            px, (bf16*)0, (bf16*)0, 0, 0, 1, D_, D4_, 1.0f);
    }

    layernorm_kernel<<<M, 256>>>(px, ln_w, ln_b, xnh, xnl);
    mm3<0><<<dim3(V_ / 128, M / 128, 1), 256, MM_SMEM>>>(
        xnh, xnl, 0, D_, worh, worl, wooh, wool, V_ / 2, 0, D_,
        out, (bf16*)0, (bf16*)0, 0, 0, 1, V_, D_, 1.0f);
    softmax_rows<<<M, 256>>>(out, V_);
}

// round 9
// speedup vs baseline: 2.7861x; 1.2080x over previous
#include <cuda_runtime.h>
#include <cuda_bf16.h>
#include <math.h>
#include <stdint.h>

#define L_   2
#define B_   2
#define S_   1024
#define D_   2048
#define H_   16
#define HD_  128
#define SKV_ 1024
#define V_   16384
#define KV2_ 2048
#define D3_  6144
#define D4_  8192
#define BS_  (B_*S_)

typedef __nv_bfloat16 bf16;

// ---------------- device scratch (allocation-free) ----------------
__device__ __align__(16) float g_x   [BS_*D_];
__device__ __align__(16) float g_qkv [BS_*D3_];
__device__ __align__(16) float g_logit[B_*H_*S_*KV2_];
__device__ __align__(16) bf16  g_xn_hi[BS_*D_],      g_xn_lo[BS_*D_];
__device__ __align__(16) bf16  g_q_hi [B_*H_*S_*HD_],   g_q_lo [B_*H_*S_*HD_];
__device__ __align__(16) bf16  g_k_hi [B_*H_*KV2_*HD_], g_k_lo [B_*H_*KV2_*HD_];
__device__ __align__(16) bf16  g_vt_hi[B_*H_*HD_*KV2_], g_vt_lo[B_*H_*HD_*KV2_];
__device__ __align__(16) bf16  g_p_hi [B_*H_*S_*KV2_],  g_p_lo [B_*H_*S_*KV2_];
__device__ __align__(16) bf16  g_h_hi [BS_*D4_],     g_h_lo [BS_*D4_];
__device__ __align__(16) bf16 w_qr_hi[L_*(D3_/2)*D_], w_qr_lo[L_*(D3_/2)*D_];
__device__ __align__(16) bf16 w_qo_hi[L_*(D3_/2)*D_], w_qo_lo[L_*(D3_/2)*D_];
__device__ __align__(16) bf16 w_1r_hi[L_*(D4_/2)*D_], w_1r_lo[L_*(D4_/2)*D_];
__device__ __align__(16) bf16 w_1o_hi[L_*(D4_/2)*D_], w_1o_lo[L_*(D4_/2)*D_];
__device__ __align__(16) bf16 w_2r_hi[L_*(D_/2)*D4_], w_2r_lo[L_*(D_/2)*D4_];
__device__ __align__(16) bf16 w_2o_hi[L_*(D_/2)*D4_], w_2o_lo[L_*(D_/2)*D4_];
__device__ __align__(16) bf16 w_or_hi[(V_/2)*D_],     w_or_lo[(V_/2)*D_];
__device__ __align__(16) bf16 w_oo_hi[(V_/2)*D_],     w_oo_lo[(V_/2)*D_];

// ---------------- helpers ----------------
__device__ __forceinline__ uint32_t smem_u32(const void* p) {
    uint32_t a;
    asm("{ .reg .u64 t; cvta.to.shared.u64 t, %1; cvt.u32.u64 %0, t; }" : "=r"(a) : "l"(p));
    return a;
}
__device__ __forceinline__ void cp16(uint32_t d, const void* g) {
    asm volatile("cp.async.cg.shared.global [%0], [%1], 16;" :: "r"(d), "l"(g));
}
#define CP_COMMIT() asm volatile("cp.async.commit_group;" ::: "memory")

#define LDX4(r, a) \
    asm volatile("ldmatrix.sync.aligned.m8n8.x4.shared.b16 {%0,%1,%2,%3}, [%4];" \
        : "=r"((r)[0]), "=r"((r)[1]), "=r"((r)[2]), "=r"((r)[3]) : "r"(a))
#define LDX2(r, a) \
    asm volatile("ldmatrix.sync.aligned.m8n8.x2.shared.b16 {%0,%1}, [%2];" \
        : "=r"((r)[0]), "=r"((r)[1]) : "r"(a))
#define MMA_BF16(c, a, b) \
    asm volatile("mma.sync.aligned.m16n8k16.row.col.f32.bf16.bf16.f32 " \
        "{%0,%1,%2,%3}, {%4,%5,%6,%7}, {%8,%9}, {%0,%1,%2,%3};" \
        : "+f"((c)[0]), "+f"((c)[1]), "+f"((c)[2]), "+f"((c)[3]) \
        : "r"((a)[0]), "r"((a)[1]), "r"((a)[2]), "r"((a)[3]), "r"((b)[0]), "r"((b)[1]))

__device__ __forceinline__ void split_store(float v, bf16* hp, bf16* lp) {
    bf16 h = __float2bfloat16(v);
    *hp = h;
    *lp = __float2bfloat16(v - __bfloat162float(h));
}
__device__ __forceinline__ void split2(float v, uint16_t& h, uint16_t& l) {
    bf16 hb = __float2bfloat16(v);
    h = __bfloat16_as_ushort(hb);
    l = __bfloat16_as_ushort(__float2bfloat16(v - __bfloat162float(hb)));
}
__device__ __forceinline__ float gelu_exact(float x) {
    return 0.5f * x * (1.0f + erff(x * 0.70710678118654752f));
}
__device__ __forceinline__ float warpSum(float v) {
    #pragma unroll
    for (int o = 16; o > 0; o >>= 1) v += __shfl_down_sync(0xffffffffu, v, o);
    return v;
}
__device__ __forceinline__ float warpMax(float v) {
    #pragma unroll
    for (int o = 16; o > 0; o >>= 1) v = fmaxf(v, __shfl_down_sync(0xffffffffu, v, o));
    return v;
}

// ================= mma.sync bf16x3 GEMM =================
// C[M,N] = alpha * A @ B^T ; fp32-equivalent via hh + h*lo + lo*h.
// CTA 128x128, 256 thr (8 warps 2x4, warp tile 64x32), K-step 32, double buffer.
// SMEM stage: Ah Al Bh Bl (10240B each); row pitch 80B -> conflict-free ldmatrix.
// __launch_bounds__(256,2): force 2 CTAs/SM (smem 2x40KBx2 = 160KB <= 228KB).
#define STG_     40960u
#define MM_SMEM  (2*40960)

template<int EPI>
__global__ __launch_bounds__(256, 2) void mm3(
    const bf16* __restrict__ Ahi, const bf16* __restrict__ Alo, long sAb, int lda,
    const bf16* __restrict__ B0hi, const bf16* __restrict__ B0lo,
    const bf16* __restrict__ B1hi, const bf16* __restrict__ B1lo,
    int nsplit, long sBb, int ldb,
    float* __restrict__ C, bf16* __restrict__ Chi, bf16* __restrict__ Clo,
    long sCb, long sCh, int Hc, int ldc,
    int K, float alpha)
{
    extern __shared__ __align__(128) char smem[];
    const uint32_t sb = smem_u32(smem);
    const int tid = threadIdx.x;
    const int lid = tid & 31, wid = tid >> 5;
    const int bz = blockIdx.z;
    const int bm = blockIdx.y * 128;
    const int bn = blockIdx.x * 128;

    const bf16* Ahb  = Ahi + (long)bz * sAb + (long)bm * lda;
    const bf16* Alb  = Alo + (long)bz * sAb + (long)bm * lda;
    const bf16* B0hb = B0hi + (long)bz * sBb;
    const bf16* B0lb = B0lo + (long)bz * sBb;
    const bf16* B1hb = B1hi ? (B1hi + (long)bz * sBb) : (const bf16*)0;
    const bf16* B1lb = B1lo ? (B1lo + (long)bz * sBb) : (const bf16*)0;

    const int i0r = tid >> 2,         i0c = tid & 3;
    const int i1r = (tid + 256) >> 2, i1c = (tid + 256) & 3;
    const int nA0 = bn + i0r, nA1 = bn + i1r;
    const bf16* bh0 = (nA0 < nsplit) ? (B0hb + (long)nA0 * ldb) : (B1hb + (long)(nA0 - nsplit) * ldb);
    const bf16* bl0 = (nA0 < nsplit) ? (B0lb + (long)nA0 * ldb) : (B1lb + (long)(nA0 - nsplit) * ldb);
    const bf16* bh1 = (nA1 < nsplit) ? (B0hb + (long)nA1 * ldb) : (B1hb + (long)(nA1 - nsplit) * ldb);
    const bf16* bl1 = (nA1 < nsplit) ? (B0lb + (long)nA1 * ldb) : (B1lb + (long)(nA1 - nsplit) * ldb);
    const bf16* ah0 = Ahb + (long)i0r * lda;
    const bf16* al0 = Alb + (long)i0r * lda;
    const bf16* ah1 = Ahb + (long)i1r * lda;
    const bf16* al1 = Alb + (long)i1r * lda;
    const uint32_t dA0 = sb + (uint32_t)i0r * 80 + (uint32_t)i0c * 16;
    const uint32_t dA1 = sb + (uint32_t)i1r * 80 + (uint32_t)i1c * 16;

    const int mbase = (wid >> 2) * 64;
    const int nbase = (wid & 3) * 32;
    const uint32_t aoff = (uint32_t)(mbase + (lid & 15)) * 80 + (uint32_t)(lid >> 4) * 16;
    const uint32_t boff = 20480u + (uint32_t)(nbase + (lid & 7)) * 80 + (uint32_t)((lid >> 3) & 1) * 16;

    float acc[4][4][4];
    #pragma unroll
    for (int a = 0; a < 4; ++a)
        #pragma unroll
        for (int b = 0; b < 4; ++b)
            #pragma unroll
            for (int c = 0; c < 4; ++c) acc[a][b][c] = 0.f;

    auto load_stage = [&](int c, int buf) {
        const uint32_t so = (uint32_t)buf * STG_;
        const int k0 = c * 32;
        const int e0 = k0 + i0c * 8, e1 = k0 + i1c * 8;
        cp16(dA0 + so,           ah0 + e0);
        cp16(dA0 + so + 10240u,  al0 + e0);
        cp16(dA1 + so,           ah1 + e1);
        cp16(dA1 + so + 10240u,  al1 + e1);
        cp16(dA0 + so + 20480u,  bh0 + e0);
        cp16(dA0 + so + 30720u,  bl0 + e0);
        cp16(dA1 + so + 20480u,  bh1 + e1);
        cp16(dA1 + so + 30720u,  bl1 + e1);
        CP_COMMIT();
    };

    const int nc = K / 32;
    load_stage(0, 0);

    for (int c = 0; c < nc; ++c) {
        const int buf = c & 1;
        if (c + 1 < nc) {
            load_stage(c + 1, buf ^ 1);
            asm volatile("cp.async.wait_group 1;" ::: "memory");
        } else {
            asm volatile("cp.async.wait_group 0;" ::: "memory");
        }
        __syncthreads();

        const uint32_t sbase = sb + (uint32_t)buf * STG_;
        #pragma unroll
        for (int kk = 0; kk < 2; ++kk) {
            uint32_t bh[4][2], bl[4][2];
            #pragma unroll
            for (int nt = 0; nt < 4; ++nt) {
                uint32_t bd = sbase + boff + (uint32_t)nt * 640 + (uint32_t)kk * 32;
                LDX2(bh[nt], bd);
                LDX2(bl[nt], bd + 10240u);
            }
            #pragma unroll
            for (int mt = 0; mt < 4; ++mt) {
                uint32_t ah[4], al[4];
                uint32_t ad = sbase + aoff + (uint32_t)mt * 1280 + (uint32_t)kk * 32;
                LDX4(ah, ad);
                LDX4(al, ad + 10240u);
                #pragma unroll
                for (int nt = 0; nt < 4; ++nt) {
                    MMA_BF16(acc[mt][nt], ah, bh[nt]);
                    MMA_BF16(acc[mt][nt], ah, bl[nt]);
                    MMA_BF16(acc[mt][nt], al, bh[nt]);
                }
            }
        }
        __syncthreads();
    }

    // ---------------- epilogue (vectorized pair stores) ----------------
    const long coff = (long)(bz / Hc) * sCb + (long)(bz % Hc) * sCh;
    #pragma unroll
    for (int mt = 0; mt < 4; ++mt) {
        #pragma unroll
        for (int half = 0; half < 2; ++half) {
            long m = bm + mbase + mt * 16 + (lid >> 2) + half * 8;
            long rbase = coff + m * (long)ldc + bn + nbase + 2 * (lid & 3);
            #pragma unroll
            for (int nt = 0; nt < 4; ++nt) {
                long idx = rbase + nt * 8;
                float v0 = acc[mt][nt][half * 2 + 0] * alpha;
                float v1 = acc[mt][nt][half * 2 + 1] * alpha;
                if (EPI == 0) {
                    *(float2*)&C[idx] = make_float2(v0, v1);
                } else if (EPI == 1) {
                    float g0 = gelu_exact(v0), g1 = gelu_exact(v1);
                    uint16_t h0, l0, h1, l1;
                    split2(g0, h0, l0);
                    split2(g1, h1, l1);
                    *(uint32_t*)&Chi[idx] = (uint32_t)h0 | ((uint32_t)h1 << 16);
                    *(uint32_t*)&Clo[idx] = (uint32_t)l0 | ((uint32_t)l1 << 16);
                } else {
                    float2 o = *(const float2*)&C[idx];
                    o.x += v0; o.y += v1;
                    *(float2*)&C[idx] = o;
                }
            }
        }
    }
}

// ================= elementwise kernels =================
// vectorized fp32 -> bf16 hi/lo (n must be multiple of 4)
__global__ void cvt_hilo4(const float4* __restrict__ x, uint2* __restrict__ hi,
                          uint2* __restrict__ lo, int n4) {
    int i = blockIdx.x * blockDim.x + threadIdx.x;
    if (i >= n4) return;
    float4 v = x[i];
    uint16_t h0, l0, h1, l1, h2, l2, h3, l3;
    split2(v.x, h0, l0); split2(v.y, h1, l1);
    split2(v.z, h2, l2); split2(v.w, h3, l3);
    hi[i] = make_uint2((uint32_t)h0 | ((uint32_t)h1 << 16), (uint32_t)h2 | ((uint32_t)h3 << 16));
    lo[i] = make_uint2((uint32_t)l0 | ((uint32_t)l1 << 16), (uint32_t)l2 | ((uint32_t)l3 << 16));
}

__global__ void pos_enc_kernel(const float* __restrict__ xin, const int* __restrict__ cpos,
                               float* __restrict__ xout) {
    int idx = blockIdx.x * blockDim.x + threadIdx.x;
    if (idx >= B_ * S_ * D_) return;
    int d = idx % D_;
    int s = (idx / D_) % S_;
    int i = d >> 1;
    float freq = expf(-(logf(10000.0f) / (float)D_) * (2.0f * (float)i));
    float ang  = (float)(cpos[0] + s) * freq;
    float pe   = (d & 1) ? cosf(ang) : sinf(ang);
    xout[idx] = xin[idx] + pe;
}

__global__ __launch_bounds__(256) void layernorm_kernel(
    const float* __restrict__ x, const float* __restrict__ w, const float* __restrict__ b,
    bf16* __restrict__ ohi, bf16* __restrict__ olo) {
    int row = blockIdx.x;
    const float* p = x + (long)row * D_;
    int tid = threadIdx.x;
    float vals[8];
    float sum = 0.f, sq = 0.f;
    #pragma unroll
    for (int k = 0; k < 8; ++k) {
        float v = p[tid + k * 256];
        vals[k] = v; sum += v; sq += v * v;
    }
    sum = warpSum(sum); sq = warpSum(sq);
    __shared__ float sh_s[8], sh_q[8];
    __shared__ float sh_mean, sh_inv;
    int wid = tid >> 5, lane = tid & 31;
    if (lane == 0) { sh_s[wid] = sum; sh_q[wid] = sq; }
    __syncthreads();
    if (tid == 0) {
        float ts = 0.f, tq = 0.f;
        #pragma unroll
        for (int k = 0; k < 8; ++k) { ts += sh_s[k]; tq += sh_q[k]; }
        float mean = ts / (float)D_;
        float var  = tq / (float)D_ - mean * mean;
        sh_mean = mean; sh_inv = rsqrtf(var + 1e-5f);
    }
    __syncthreads();
    float mean = sh_mean, inv = sh_inv;
    long base = (long)row * D_;
    #pragma unroll
    for (int k = 0; k < 8; ++k) {
        int c = tid + k * 256;
        float y = (vals[k] - mean) * inv * w[c] + b[c];
        split_store(y, &ohi[base + c], &olo[base + c]);
    }
}

// Q gather, vectorized by 4 along d
__global__ void gather_q_kernel(uint2* __restrict__ hi, uint2* __restrict__ lo) {
    int i4 = blockIdx.x * blockDim.x + threadIdx.x;
    if (i4 >= (B_ * H_ * S_ * HD_) / 4) return;
    int idx = i4 * 4;
    int d = idx % HD_;
    int s = (idx / HD_) % S_;
    int h = (idx / (HD_ * S_)) % H_;
    int b = idx / (HD_ * S_ * H_);
    float4 v = *(const float4*)&g_qkv[(long)(b * S_ + s) * D3_ + h * (3 * HD_) + d];
    uint16_t h0, l0, h1, l1, h2, l2, h3, l3;
    split2(v.x, h0, l0); split2(v.y, h1, l1);
    split2(v.z, h2, l2); split2(v.w, h3, l3);
    hi[i4] = make_uint2((uint32_t)h0 | ((uint32_t)h1 << 16), (uint32_t)h2 | ((uint32_t)h3 << 16));
    lo[i4] = make_uint2((uint32_t)l0 | ((uint32_t)l1 << 16), (uint32_t)l2 | ((uint32_t)l3 << 16));
}

// K gather, vectorized by 4 along d
__global__ void gather_k_kernel(const float* __restrict__ res, const float* __restrict__ off,
                                int layer, uint2* __restrict__ hi, uint2* __restrict__ lo) {
    int i4 = blockIdx.x * blockDim.x + threadIdx.x;
    if (i4 >= (B_ * H_ * KV2_ * HD_) / 4) return;
    int idx = i4 * 4;
    int d = idx % HD_;
    int j = (idx / HD_) % KV2_;
    int h = (idx / (HD_ * KV2_)) % H_;
    int b = idx / (HD_ * KV2_ * H_);
    float4 v;
    if (j < SKV_) {
        v = *(const float4*)&res[((((long)layer * B_ + b) * H_ + h) * SKV_ + j) * HD_ + d];
    } else {
        int j2 = j - SKV_;
        if (j2 == SKV_ - 1)
            v = *(const float4*)&g_qkv[(long)(b * S_ + (S_ - 1)) * D3_ + h * (3 * HD_) + HD_ + d];
        else
            v = *(const float4*)&off[((((long)layer * B_ + b) * H_ + h) * SKV_ + j2) * HD_ + d];
    }
    uint16_t h0, l0, h1, l1, h2, l2, h3, l3;
    split2(v.x, h0, l0); split2(v.y, h1, l1);
    split2(v.z, h2, l2); split2(v.w, h3, l3);
    hi[i4] = make_uint2((uint32_t)h0 | ((uint32_t)h1 << 16), (uint32_t)h2 | ((uint32_t)h3 << 16));
    lo[i4] = make_uint2((uint32_t)l0 | ((uint32_t)l1 << 16), (uint32_t)l2 | ((uint32_t)l3 << 16));
}

// V^T gather via smem tiled transpose: coalesced read (d) and write (j).
// grid: (KV2/32, HD/32, B*H), block (32,8)
__global__ __launch_bounds__(256) void gather_vt_kernel(
    const float* __restrict__ res, const float* __restrict__ off, int layer,
    bf16* __restrict__ hi, bf16* __restrict__ lo) {
    __shared__ float t[32][33];
    const int jt = blockIdx.x * 32;
    const int dt = blockIdx.y * 32;
    const int bh = blockIdx.z;
    const int h = bh % H_, b = bh / H_;
    const int tx = threadIdx.x, ty = threadIdx.y;

    #pragma unroll
    for (int r = 0; r < 4; ++r) {
        int j = jt + ty + r * 8;
        int d = dt + tx;
        float v;
        if (j < SKV_) {
            v = res[((((long)layer * B_ + b) * H_ + h) * SKV_ + j) * HD_ + d];
        } else {
            int j2 = j - SKV_;
            if (j2 == SKV_ - 1)
                v = g_qkv[(long)(b * S_ + (S_ - 1)) * D3_ + h * (3 * HD_) + 2 * HD_ + d];
            else
                v = off[((((long)layer * B_ + b) * H_ + h) * SKV_ + j2) * HD_ + d];
        }
        t[ty + r * 8][tx] = v;
    }
    __syncthreads();
    #pragma unroll
    for (int r = 0; r < 4; ++r) {
        int d = dt + ty + r * 8;
        int j = jt + tx;
        long o = ((long)bh * HD_ + d) * KV2_ + j;
        split_store(t[tx][ty + r * 8], &hi[o], &lo[o]);
    }
}

// softmax over width 2048 -> split bf16 hi/lo (vectorized)
__global__ __launch_bounds__(256) void softmax_p(const float* __restrict__ logit,
                                                 uint4* __restrict__ phi, uint4* __restrict__ plo) {
    long row = blockIdx.x;
    const float4* p = (const float4*)(logit + row * KV2_);
    int tid = threadIdx.x;
    int wid = tid >> 5, lane = tid & 31;
    __shared__ float sh[8];
    __shared__ float sh_b;
    float4 va = p[tid * 2], vb = p[tid * 2 + 1];
    float vals[8] = {va.x, va.y, va.z, va.w, vb.x, vb.y, vb.z, vb.w};
    float m = -3.0e38f;
    #pragma unroll
    for (int k = 0; k < 8; ++k) m = fmaxf(m, vals[k]);
    m = warpMax(m);
    if (lane == 0) sh[wid] = m;
    __syncthreads();
    if (tid == 0) {
        float t = sh[0];
        #pragma unroll
        for (int k = 1; k < 8; ++k) t = fmaxf(t, sh[k]);
        sh_b = t;
    }
    __syncthreads();
    m = sh_b;
    float s = 0.f;
    #pragma unroll
    for (int k = 0; k < 8; ++k) { vals[k] = expf(vals[k] - m); s += vals[k]; }
    s = warpSum(s);
    if (lane == 0) sh[wid] = s;
    __syncthreads();
    if (tid == 0) {
        float t = 0.f;
        #pragma unroll
        for (int k = 0; k < 8; ++k) t += sh[k];
        sh_b = t;
    }
    __syncthreads();
    float inv = 1.0f / sh_b;
    uint16_t hh[8], ll[8];
    #pragma unroll
    for (int k = 0; k < 8; ++k) split2(vals[k] * inv, hh[k], ll[k]);
    uint4 ho, lov;
    ho.x = (uint32_t)hh[0] | ((uint32_t)hh[1] << 16);
    ho.y = (uint32_t)hh[2] | ((uint32_t)hh[3] << 16);
    ho.z = (uint32_t)hh[4] | ((uint32_t)hh[5] << 16);
    ho.w = (uint32_t)hh[6] | ((uint32_t)hh[7] << 16);
    lov.x = (uint32_t)ll[0] | ((uint32_t)ll[1] << 16);
    lov.y = (uint32_t)ll[2] | ((uint32_t)ll[3] << 16);
    lov.z = (uint32_t)ll[4] | ((uint32_t)ll[5] << 16);
    lov.w = (uint32_t)ll[6] | ((uint32_t)ll[7] << 16);
    phi[row * 256 + tid] = ho;
    plo[row * 256 + tid] = lov;
}

__global__ __launch_bounds__(256) void softmax_rows(float* __restrict__ data, int width) {
    long row = blockIdx.x;
    float* p = data + row * (long)width;
    int tid = threadIdx.x;
    int wid = tid >> 5, lane = tid & 31;
    __shared__ float sh[8];
    __shared__ float sh_b;
    float m = -3.0e38f;
    for (int c = tid; c < width; c += 256) m = fmaxf(m, p[c]);
    m = warpMax(m);
    if (lane == 0) sh[wid] = m;
    __syncthreads();
    if (tid == 0) {
        float t = sh[0];
        #pragma unroll
        for (int k = 1; k < 8; ++k) t = fmaxf(t, sh[k]);
        sh_b = t;
    }
    __syncthreads();
    m = sh_b;
    float s = 0.f;
    for (int c = tid; c < width; c += 256) {
        float e = expf(p[c] - m);
        p[c] = e; s += e;
    }
    s = warpSum(s);
    if (lane == 0) sh[wid] = s;
    __syncthreads();
    if (tid == 0) {
        float t = 0.f;
        #pragma unroll
        for (int k = 0; k < 8; ++k) t += sh[k];
        sh_b = t;
    }
    __syncthreads();
    float inv = 1.0f / sh_b;
    for (int c = tid; c < width; c += 256) p[c] *= inv;
}

// ================= host orchestration =================
extern "C" void kernel_launch(void* const* d_in, const int* in_sizes, int n_in,
                              void* d_out, int out_size) {
    const float* x_in  = (const float*)d_in[0];
    const float* ln_w  = (const float*)d_in[1];
    const float* ln_b  = (const float*)d_in[2];
    const float* qkv_r = (const float*)d_in[3];
    const float* qkv_o = (const float*)d_in[4];
    const float* k_res = (const float*)d_in[5];
    const float* v_res = (const float*)d_in[6];
    const float* k_off = (const float*)d_in[7];
    const float* v_off = (const float*)d_in[8];
    const float* f1_r  = (const float*)d_in[9];
    const float* f1_o  = (const float*)d_in[10];
    const float* f2_r  = (const float*)d_in[11];
    const float* f2_o  = (const float*)d_in[12];
    const float* o_res = (const float*)d_in[13];
    const float* o_off = (const float*)d_in[14];
    const int*   cpos  = (const int*)d_in[15];
    float* out = (float*)d_out;

    #define GSA(p, sym) void* p##_v; cudaGetSymbolAddress(&p##_v, sym); auto p = (decltype(&sym[0]))p##_v
    GSA(px, g_x);       GSA(pqkv, g_qkv);   GSA(plog, g_logit);
    GSA(xnh, g_xn_hi);  GSA(xnl, g_xn_lo);
    GSA(qh, g_q_hi);    GSA(ql, g_q_lo);
    GSA(kh, g_k_hi);    GSA(kl, g_k_lo);
    GSA(vth, g_vt_hi);  GSA(vtl, g_vt_lo);
    GSA(pph, g_p_hi);   GSA(ppl, g_p_lo);
    GSA(hh, g_h_hi);    GSA(hl, g_h_lo);
    GSA(qrh, w_qr_hi);  GSA(qrl, w_qr_lo);  GSA(qoh, w_qo_hi);  GSA(qol, w_qo_lo);
    GSA(w1rh, w_1r_hi); GSA(w1rl, w_1r_lo); GSA(w1oh, w_1o_hi); GSA(w1ol, w_1o_lo);
    GSA(w2rh, w_2r_hi); GSA(w2rl, w_2r_lo); GSA(w2oh, w_2o_hi); GSA(w2ol, w_2o_lo);
    GSA(worh, w_or_hi); GSA(worl, w_or_lo); GSA(wooh, w_oo_hi); GSA(wool, w_oo_lo);
    #undef GSA

    cudaFuncSetAttribute(mm3<0>, cudaFuncAttributeMaxDynamicSharedMemorySize, MM_SMEM);
    cudaFuncSetAttribute(mm3<1>, cudaFuncAttributeMaxDynamicSharedMemorySize, MM_SMEM);
    cudaFuncSetAttribute(mm3<2>, cudaFuncAttributeMaxDynamicSharedMemorySize, MM_SMEM);

    const int NOSPLIT = 0x7fffffff;
    const float attn_scale = 0.08838834764831845f;
    const int M = BS_;

    // weight conversion fp32 -> bf16 hi/lo (vectorized x4)
    #define CVT(src, dsth, dstl, n) \
        cvt_hilo4<<<((n) / 4 + 255) / 256, 256>>>((const float4*)(src), (uint2*)(dsth), (uint2*)(dstl), (n) / 4)
    const int nQ = L_ * (D3_ / 2) * D_;
    const int n1 = L_ * (D4_ / 2) * D_;
    const int n2 = L_ * (D_ / 2) * D4_;
    const int nO = (V_ / 2) * D_;
    CVT(qkv_r, qrh, qrl, nQ);
    CVT(qkv_o, qoh, qol, nQ);
    CVT(f1_r, w1rh, w1rl, n1);
    CVT(f1_o, w1oh, w1ol, n1);
    CVT(f2_r, w2rh, w2rl, n2);
    CVT(f2_o, w2oh, w2ol, n2);
    CVT(o_res, worh, worl, nO);
    CVT(o_off, wooh, wool, nO);
    #undef CVT

    pos_enc_kernel<<<(B_ * S_ * D_ + 255) / 256, 256>>>(x_in, cpos, px);

    for (int i = 0; i < L_; ++i) {
        const long oq = (long)i * (D3_ / 2) * D_;
        const long o1 = (long)i * (D4_ / 2) * D_;
        const long o2 = (long)i * (D_ / 2) * D4_;

        // ---- attention ----
        layernorm_kernel<<<M, 256>>>(px, ln_w, ln_b, xnh, xnl);

        mm3<0><<<dim3(D3_ / 128, M / 128, 1), 256, MM_SMEM>>>(
            xnh, xnl, 0, D_, qrh + oq, qrl + oq, qoh + oq, qol + oq, D3_ / 2, 0, D_,
            pqkv, (bf16*)0, (bf16*)0, 0, 0, 1, D3_, D_, 1.0f);

        gather_q_kernel<<<(B_ * H_ * S_ * HD_ / 4 + 255) / 256, 256>>>((uint2*)qh, (uint2*)ql);
        gather_k_kernel<<<(B_ * H_ * KV2_ * HD_ / 4 + 255) / 256, 256>>>(k_res, k_off, i, (uint2*)kh, (uint2*)kl);
        gather_vt_kernel<<<dim3(KV2_ / 32, HD_ / 32, B_ * H_), dim3(32, 8)>>>(v_res, v_off, i, vth, vtl);

        // logits = scale * Q @ K^T : batch 32, M=1024, N=2048, K=128
        mm3<0><<<dim3(KV2_ / 128, S_ / 128, B_ * H_), 256, MM_SMEM>>>(
            qh, ql, (long)S_ * HD_, HD_, kh, kl, (bf16*)0, (bf16*)0, NOSPLIT,
            (long)KV2_ * HD_, HD_,
            plog, (bf16*)0, (bf16*)0, (long)S_ * KV2_, 0, 1, KV2_, HD_, attn_scale);

        softmax_p<<<B_ * H_ * S_, 256>>>(plog, (uint4*)pph, (uint4*)ppl);

        // x += P @ V : batch 32, M=1024, N=128, K=2048; scatter to head offset
        mm3<2><<<dim3(1, S_ / 128, B_ * H_), 256, MM_SMEM>>>(
            pph, ppl, (long)S_ * KV2_, KV2_, vth, vtl, (bf16*)0, (bf16*)0, NOSPLIT,
            (long)HD_ * KV2_, KV2_,
            px, (bf16*)0, (bf16*)0, (long)S_ * D_, HD_, H_, D_, KV2_, 1.0f);

        // ---- FFN ----
        layernorm_kernel<<<M, 256>>>(px, ln_w, ln_b, xnh, xnl);

        mm3<1><<<dim3(D4_ / 128, M / 128, 1), 256, MM_SMEM>>>(
            xnh, xnl, 0, D_, w1rh + o1, w1rl + o1, w1oh + o1, w1ol + o1, D4_ / 2, 0, D_,
            (float*)0, hh, hl, 0, 0, 1, D4_, D_, 1.0f);

        mm3<2><<<dim3(D_ / 128, M / 128, 1), 256, MM_SMEM>>>(
            hh, hl, 0, D4_, w2rh + o2, w2rl + o2, w2oh + o2, w2ol + o2, D_ / 2, 0, D4_,
            px, (bf16*)0, (bf16*)0, 0, 0, 1, D_, D4_, 1.0f);
    }

    layernorm_kernel<<<M, 256>>>(px, ln_w, ln_b, xnh, xnl);
    mm3<0><<<dim3(V_ / 128, M / 128, 1), 256, MM_SMEM>>>(
        xnh, xnl, 0, D_, worh, worl, wooh, wool, V_ / 2, 0, D_,
        out, (bf16*)0, (bf16*)0, 0, 0, 1, V_, D_, 1.0f);
    softmax_rows<<<M, 256>>>(out, V_);
}

// round 10
// speedup vs baseline: 2.8783x; 1.0331x over previous
#include <cuda_runtime.h>
#include <cuda_bf16.h>
#include <math.h>
#include <stdint.h>

#define L_   2
#define B_   2
#define S_   1024
#define D_   2048
#define H_   16
#define HD_  128
#define SKV_ 1024
#define V_   16384
#define KV2_ 2048
#define D3_  6144
#define D4_  8192
#define BS_  (B_*S_)

typedef __nv_bfloat16 bf16;

// ---------------- device scratch (allocation-free) ----------------
__device__ __align__(16) float g_x   [BS_*D_];
__device__ __align__(16) float g_qkv [BS_*D3_];
__device__ __align__(16) bf16  g_xn_hi[BS_*D_],      g_xn_lo[BS_*D_];
__device__ __align__(16) bf16  g_k_hi [B_*H_*KV2_*HD_], g_k_lo [B_*H_*KV2_*HD_];
__device__ __align__(16) bf16  g_vt_hi[B_*H_*HD_*KV2_], g_vt_lo[B_*H_*HD_*KV2_];
__device__ __align__(16) bf16  g_h_hi [BS_*D4_],     g_h_lo [BS_*D4_];
__device__ __align__(16) bf16 w_qr_hi[L_*(D3_/2)*D_], w_qr_lo[L_*(D3_/2)*D_];
__device__ __align__(16) bf16 w_qo_hi[L_*(D3_/2)*D_], w_qo_lo[L_*(D3_/2)*D_];
__device__ __align__(16) bf16 w_1r_hi[L_*(D4_/2)*D_], w_1r_lo[L_*(D4_/2)*D_];
__device__ __align__(16) bf16 w_1o_hi[L_*(D4_/2)*D_], w_1o_lo[L_*(D4_/2)*D_];
__device__ __align__(16) bf16 w_2r_hi[L_*(D_/2)*D4_], w_2r_lo[L_*(D_/2)*D4_];
__device__ __align__(16) bf16 w_2o_hi[L_*(D_/2)*D4_], w_2o_lo[L_*(D_/2)*D4_];
__device__ __align__(16) bf16 w_or_hi[(V_/2)*D_],     w_or_lo[(V_/2)*D_];
__device__ __align__(16) bf16 w_oo_hi[(V_/2)*D_],     w_oo_lo[(V_/2)*D_];

// ---------------- helpers ----------------
__device__ __forceinline__ uint32_t smem_u32(const void* p) {
    uint32_t a;
    asm("{ .reg .u64 t; cvta.to.shared.u64 t, %1; cvt.u32.u64 %0, t; }" : "=r"(a) : "l"(p));
    return a;
}
__device__ __forceinline__ void cp16(uint32_t d, const void* g) {
    asm volatile("cp.async.cg.shared.global [%0], [%1], 16;" :: "r"(d), "l"(g));
}
#define CP_COMMIT() asm volatile("cp.async.commit_group;" ::: "memory")

#define LDX4(r, a) \
    asm volatile("ldmatrix.sync.aligned.m8n8.x4.shared.b16 {%0,%1,%2,%3}, [%4];" \
        : "=r"((r)[0]), "=r"((r)[1]), "=r"((r)[2]), "=r"((r)[3]) : "r"(a))
#define LDX2(r, a) \
    asm volatile("ldmatrix.sync.aligned.m8n8.x2.shared.b16 {%0,%1}, [%2];" \
        : "=r"((r)[0]), "=r"((r)[1]) : "r"(a))
#define MMA_BF16(c, a, b) \
    asm volatile("mma.sync.aligned.m16n8k16.row.col.f32.bf16.bf16.f32 " \
        "{%0,%1,%2,%3}, {%4,%5,%6,%7}, {%8,%9}, {%0,%1,%2,%3};" \
        : "+f"((c)[0]), "+f"((c)[1]), "+f"((c)[2]), "+f"((c)[3]) \
        : "r"((a)[0]), "r"((a)[1]), "r"((a)[2]), "r"((a)[3]), "r"((b)[0]), "r"((b)[1]))

__device__ __forceinline__ void split_store(float v, bf16* hp, bf16* lp) {
    bf16 h = __float2bfloat16(v);
    *hp = h;
    *lp = __float2bfloat16(v - __bfloat162float(h));
}
__device__ __forceinline__ void split2(float v, uint16_t& h, uint16_t& l) {
    bf16 hb = __float2bfloat16(v);
    h = __bfloat16_as_ushort(hb);
    l = __bfloat16_as_ushort(__float2bfloat16(v - __bfloat162float(hb)));
}
__device__ __forceinline__ void packsplit(float a, float b, uint32_t& h, uint32_t& l) {
    uint16_t ha, la, hb, lb;
    split2(a, ha, la); split2(b, hb, lb);
    h = (uint32_t)ha | ((uint32_t)hb << 16);
    l = (uint32_t)la | ((uint32_t)lb << 16);
}
__device__ __forceinline__ float gelu_exact(float x) {
    return 0.5f * x * (1.0f + erff(x * 0.70710678118654752f));
}
__device__ __forceinline__ float warpSum(float v) {
    #pragma unroll
    for (int o = 16; o > 0; o >>= 1) v += __shfl_down_sync(0xffffffffu, v, o);
    return v;
}
__device__ __forceinline__ float warpMax(float v) {
    #pragma unroll
    for (int o = 16; o > 0; o >>= 1) v = fmaxf(v, __shfl_down_sync(0xffffffffu, v, o));
    return v;
}

// ================= mma.sync bf16x3 GEMM (unchanged core) =================
#define STG_     40960u
#define MM_SMEM  (2*40960)

template<int EPI>
__global__ __launch_bounds__(256, 2) void mm3(
    const bf16* __restrict__ Ahi, const bf16* __restrict__ Alo, long sAb, int lda,
    const bf16* __restrict__ B0hi, const bf16* __restrict__ B0lo,
    const bf16* __restrict__ B1hi, const bf16* __restrict__ B1lo,
    int nsplit, long sBb, int ldb,
    float* __restrict__ C, bf16* __restrict__ Chi, bf16* __restrict__ Clo,
    long sCb, long sCh, int Hc, int ldc,
    int K, float alpha)
{
    extern __shared__ __align__(128) char smem[];
    const uint32_t sb = smem_u32(smem);
    const int tid = threadIdx.x;
    const int lid = tid & 31, wid = tid >> 5;
    const int bz = blockIdx.z;
    const int bm = blockIdx.y * 128;
    const int bn = blockIdx.x * 128;

    const bf16* Ahb  = Ahi + (long)bz * sAb + (long)bm * lda;
    const bf16* Alb  = Alo + (long)bz * sAb + (long)bm * lda;
    const bf16* B0hb = B0hi + (long)bz * sBb;
    const bf16* B0lb = B0lo + (long)bz * sBb;
    const bf16* B1hb = B1hi ? (B1hi + (long)bz * sBb) : (const bf16*)0;
    const bf16* B1lb = B1lo ? (B1lo + (long)bz * sBb) : (const bf16*)0;

    const int i0r = tid >> 2,         i0c = tid & 3;
    const int i1r = (tid + 256) >> 2, i1c = (tid + 256) & 3;
    const int nA0 = bn + i0r, nA1 = bn + i1r;
    const bf16* bh0 = (nA0 < nsplit) ? (B0hb + (long)nA0 * ldb) : (B1hb + (long)(nA0 - nsplit) * ldb);
    const bf16* bl0 = (nA0 < nsplit) ? (B0lb + (long)nA0 * ldb) : (B1lb + (long)(nA0 - nsplit) * ldb);
    const bf16* bh1 = (nA1 < nsplit) ? (B0hb + (long)nA1 * ldb) : (B1hb + (long)(nA1 - nsplit) * ldb);
    const bf16* bl1 = (nA1 < nsplit) ? (B0lb + (long)nA1 * ldb) : (B1lb + (long)(nA1 - nsplit) * ldb);
    const bf16* ah0 = Ahb + (long)i0r * lda;
    const bf16* al0 = Alb + (long)i0r * lda;
    const bf16* ah1 = Ahb + (long)i1r * lda;
    const bf16* al1 = Alb + (long)i1r * lda;
    const uint32_t dA0 = sb + (uint32_t)i0r * 80 + (uint32_t)i0c * 16;
    const uint32_t dA1 = sb + (uint32_t)i1r * 80 + (uint32_t)i1c * 16;

    const int mbase = (wid >> 2) * 64;
    const int nbase = (wid & 3) * 32;
    const uint32_t aoff = (uint32_t)(mbase + (lid & 15)) * 80 + (uint32_t)(lid >> 4) * 16;
    const uint32_t boff = 20480u + (uint32_t)(nbase + (lid & 7)) * 80 + (uint32_t)((lid >> 3) & 1) * 16;

    float acc[4][4][4];
    #pragma unroll
    for (int a = 0; a < 4; ++a)
        #pragma unroll
        for (int b = 0; b < 4; ++b)
            #pragma unroll
            for (int c = 0; c < 4; ++c) acc[a][b][c] = 0.f;

    auto load_stage = [&](int c, int buf) {
        const uint32_t so = (uint32_t)buf * STG_;
        const int k0 = c * 32;
        const int e0 = k0 + i0c * 8, e1 = k0 + i1c * 8;
        cp16(dA0 + so,           ah0 + e0);
        cp16(dA0 + so + 10240u,  al0 + e0);
        cp16(dA1 + so,           ah1 + e1);
        cp16(dA1 + so + 10240u,  al1 + e1);
        cp16(dA0 + so + 20480u,  bh0 + e0);
        cp16(dA0 + so + 30720u,  bl0 + e0);
        cp16(dA1 + so + 20480u,  bh1 + e1);
        cp16(dA1 + so + 30720u,  bl1 + e1);
        CP_COMMIT();
    };

    const int nc = K / 32;
    load_stage(0, 0);

    for (int c = 0; c < nc; ++c) {
        const int buf = c & 1;
        if (c + 1 < nc) {
            load_stage(c + 1, buf ^ 1);
            asm volatile("cp.async.wait_group 1;" ::: "memory");
        } else {
            asm volatile("cp.async.wait_group 0;" ::: "memory");
        }
        __syncthreads();

        const uint32_t sbase = sb + (uint32_t)buf * STG_;
        #pragma unroll
        for (int kk = 0; kk < 2; ++kk) {
            uint32_t bh[4][2], bl[4][2];
            #pragma unroll
            for (int nt = 0; nt < 4; ++nt) {
                uint32_t bd = sbase + boff + (uint32_t)nt * 640 + (uint32_t)kk * 32;
                LDX2(bh[nt], bd);
                LDX2(bl[nt], bd + 10240u);
            }
            #pragma unroll
            for (int mt = 0; mt < 4; ++mt) {
                uint32_t ah[4], al[4];
                uint32_t ad = sbase + aoff + (uint32_t)mt * 1280 + (uint32_t)kk * 32;
                LDX4(ah, ad);
                LDX4(al, ad + 10240u);
                #pragma unroll
                for (int nt = 0; nt < 4; ++nt) {
                    MMA_BF16(acc[mt][nt], ah, bh[nt]);
                    MMA_BF16(acc[mt][nt], ah, bl[nt]);
                    MMA_BF16(acc[mt][nt], al, bh[nt]);
                }
            }
        }
        __syncthreads();
    }

    const long coff = (long)(bz / Hc) * sCb + (long)(bz % Hc) * sCh;
    #pragma unroll
    for (int mt = 0; mt < 4; ++mt) {
        #pragma unroll
        for (int half = 0; half < 2; ++half) {
            long m = bm + mbase + mt * 16 + (lid >> 2) + half * 8;
            long rbase = coff + m * (long)ldc + bn + nbase + 2 * (lid & 3);
            #pragma unroll
            for (int nt = 0; nt < 4; ++nt) {
                long idx = rbase + nt * 8;
                float v0 = acc[mt][nt][half * 2 + 0] * alpha;
                float v1 = acc[mt][nt][half * 2 + 1] * alpha;
                if (EPI == 0) {
                    *(float2*)&C[idx] = make_float2(v0, v1);
                } else if (EPI == 1) {
                    float g0 = gelu_exact(v0), g1 = gelu_exact(v1);
                    uint32_t hh, ll;
                    packsplit(g0, g1, hh, ll);
                    *(uint32_t*)&Chi[idx] = hh;
                    *(uint32_t*)&Clo[idx] = ll;
                } else {
                    float2 o = *(const float2*)&C[idx];
                    o.x += v0; o.y += v1;
                    *(float2*)&C[idx] = o;
                }
            }
        }
    }
}

// ================= fused flash attention =================
// grid (S/128, B*H), 256 thr (8 warps x 16 q-rows). Q in regs (pre-scaled bf16 hi/lo).
// KV streamed in 64-key tiles, double-buffered cp.async from pre-gathered bf16 hi/lo.
// SMEM buffer: Khi[64x272B] Klo VThi[128x144B] VTlo = 71680B/buf, 2 bufs = 143360.
#define FA_SMEM 143360

__global__ __launch_bounds__(256, 1) void flash_attn(
    const bf16* __restrict__ khi, const bf16* __restrict__ klo,
    const bf16* __restrict__ vthi, const bf16* __restrict__ vtlo,
    float* __restrict__ x)
{
    extern __shared__ __align__(128) char smem[];
    const uint32_t sb = smem_u32(smem);
    const int tid = threadIdx.x, lid = tid & 31, wid = tid >> 5;
    const int qt = blockIdx.x, bh = blockIdx.y;
    const int b = bh / H_, h = bh % H_;

    // ---- Q fragments: rows r0, r0+8; pre-scaled; bf16 hi/lo ----
    const int r0 = wid * 16 + (lid >> 2);
    const int c2 = (lid & 3) * 2;
    const float* q0 = g_qkv + (long)(b * S_ + qt * 128 + r0) * D3_ + h * (3 * HD_);
    const float* q1 = q0 + 8 * D3_;
    const float scale = 0.08838834764831845f;
    uint32_t ah[8][4], al[8][4];
    #pragma unroll
    for (int kt = 0; kt < 8; ++kt) {
        float2 v0 = *(const float2*)(q0 + kt * 16 + c2);
        float2 v1 = *(const float2*)(q1 + kt * 16 + c2);
        float2 v2 = *(const float2*)(q0 + kt * 16 + c2 + 8);
        float2 v3 = *(const float2*)(q1 + kt * 16 + c2 + 8);
        packsplit(v0.x * scale, v0.y * scale, ah[kt][0], al[kt][0]);
        packsplit(v1.x * scale, v1.y * scale, ah[kt][1], al[kt][1]);
        packsplit(v2.x * scale, v2.y * scale, ah[kt][2], al[kt][2]);
        packsplit(v3.x * scale, v3.y * scale, ah[kt][3], al[kt][3]);
    }

    float o[16][4];
    #pragma unroll
    for (int i = 0; i < 16; ++i)
        #pragma unroll
        for (int j = 0; j < 4; ++j) o[i][j] = 0.f;
    float m0 = -1e30f, m1 = -1e30f, l0 = 0.f, l1 = 0.f;

    const uint32_t koff = (uint32_t)((lid & 15) * 272 + ((lid >> 4) & 1) * 16);
    const uint32_t voff = (uint32_t)((lid & 15) * 144 + ((lid >> 4) & 1) * 16);

    auto load_stage = [&](int t, int buf) {
        const uint32_t so = sb + (uint32_t)buf * 71680u;
        const int kv0 = t * 64;
        for (int i = tid; i < 1024; i += 256) {
            int row = i >> 4, c16 = i & 15;
            long gk = ((long)bh * KV2_ + kv0 + row) * HD_ + c16 * 8;
            uint32_t d = so + (uint32_t)row * 272u + (uint32_t)c16 * 16u;
            cp16(d, khi + gk);
            cp16(d + 17408u, klo + gk);
        }
        for (int i = tid; i < 1024; i += 256) {
            int row = i >> 3, c = i & 7;
            long gv = ((long)bh * HD_ + row) * KV2_ + kv0 + c * 8;
            uint32_t d = so + 34816u + (uint32_t)row * 144u + (uint32_t)c * 16u;
            cp16(d, vthi + gv);
            cp16(d + 18432u, vtlo + gv);
        }
        CP_COMMIT();
    };

    load_stage(0, 0);

    for (int t = 0; t < KV2_ / 64; ++t) {
        const int buf = t & 1;
        if (t + 1 < KV2_ / 64) {
            load_stage(t + 1, buf ^ 1);
            asm volatile("cp.async.wait_group 1;" ::: "memory");
        } else {
            asm volatile("cp.async.wait_group 0;" ::: "memory");
        }
        __syncthreads();

        const uint32_t kb = sb + (uint32_t)buf * 71680u;
        const uint32_t vb = kb + 34816u;

        // ---- QK^T: P[128q x 64kv] ----
        float pacc[8][4];
        #pragma unroll
        for (int j = 0; j < 8; ++j)
            #pragma unroll
            for (int q = 0; q < 4; ++q) pacc[j][q] = 0.f;

        #pragma unroll
        for (int kt = 0; kt < 8; ++kt) {
            #pragma unroll
            for (int np = 0; np < 4; ++np) {
                uint32_t th[4], tl[4];
                uint32_t ad = kb + (uint32_t)np * 4352u + (uint32_t)kt * 32u + koff;
                LDX4(th, ad);
                LDX4(tl, ad + 17408u);
                uint32_t b0h[2] = {th[0], th[2]}, b1h[2] = {th[1], th[3]};
                uint32_t b0l[2] = {tl[0], tl[2]}, b1l[2] = {tl[1], tl[3]};
                MMA_BF16(pacc[2*np],   ah[kt], b0h);
                MMA_BF16(pacc[2*np],   al[kt], b0h);
                MMA_BF16(pacc[2*np],   ah[kt], b0l);
                MMA_BF16(pacc[2*np+1], ah[kt], b1h);
                MMA_BF16(pacc[2*np+1], al[kt], b1h);
                MMA_BF16(pacc[2*np+1], ah[kt], b1l);
            }
        }

        // ---- online softmax ----
        float tm0 = -1e30f, tm1 = -1e30f;
        #pragma unroll
        for (int j = 0; j < 8; ++j) {
            tm0 = fmaxf(tm0, fmaxf(pacc[j][0], pacc[j][1]));
            tm1 = fmaxf(tm1, fmaxf(pacc[j][2], pacc[j][3]));
        }
        tm0 = fmaxf(tm0, __shfl_xor_sync(0xffffffffu, tm0, 1));
        tm0 = fmaxf(tm0, __shfl_xor_sync(0xffffffffu, tm0, 2));
        tm1 = fmaxf(tm1, __shfl_xor_sync(0xffffffffu, tm1, 1));
        tm1 = fmaxf(tm1, __shfl_xor_sync(0xffffffffu, tm1, 2));
        float mn0 = fmaxf(m0, tm0), mn1 = fmaxf(m1, tm1);
        float corr0 = __expf(m0 - mn0), corr1 = __expf(m1 - mn1);
        m0 = mn0; m1 = mn1;
        float s0 = 0.f, s1 = 0.f;
        #pragma unroll
        for (int j = 0; j < 8; ++j) {
            pacc[j][0] = __expf(pacc[j][0] - m0);
            pacc[j][1] = __expf(pacc[j][1] - m0);
            pacc[j][2] = __expf(pacc[j][2] - m1);
            pacc[j][3] = __expf(pacc[j][3] - m1);
            s0 += pacc[j][0] + pacc[j][1];
            s1 += pacc[j][2] + pacc[j][3];
        }
        s0 += __shfl_xor_sync(0xffffffffu, s0, 1);
        s0 += __shfl_xor_sync(0xffffffffu, s0, 2);
        s1 += __shfl_xor_sync(0xffffffffu, s1, 1);
        s1 += __shfl_xor_sync(0xffffffffu, s1, 2);
        l0 = l0 * corr0 + s0;
        l1 = l1 * corr1 + s1;
        #pragma unroll
        for (int nt = 0; nt < 16; ++nt) {
            o[nt][0] *= corr0; o[nt][1] *= corr0;
            o[nt][2] *= corr1; o[nt][3] *= corr1;
        }

        // ---- PV: O += P~ @ V (P~ frags straight from pacc) ----
        #pragma unroll
        for (int kt = 0; kt < 4; ++kt) {
            uint32_t ap[4], lp[4];
            packsplit(pacc[2*kt][0],   pacc[2*kt][1],   ap[0], lp[0]);
            packsplit(pacc[2*kt][2],   pacc[2*kt][3],   ap[1], lp[1]);
            packsplit(pacc[2*kt+1][0], pacc[2*kt+1][1], ap[2], lp[2]);
            packsplit(pacc[2*kt+1][2], pacc[2*kt+1][3], ap[3], lp[3]);
            #pragma unroll
            for (int np = 0; np < 8; ++np) {
                uint32_t th[4], tl[4];
                uint32_t ad = vb + (uint32_t)np * 2304u + (uint32_t)kt * 32u + voff;
                LDX4(th, ad);
                LDX4(tl, ad + 18432u);
                uint32_t b0h[2] = {th[0], th[2]}, b1h[2] = {th[1], th[3]};
                uint32_t b0l[2] = {tl[0], tl[2]}, b1l[2] = {tl[1], tl[3]};
                MMA_BF16(o[2*np],   ap, b0h);
                MMA_BF16(o[2*np],   lp, b0h);
                MMA_BF16(o[2*np],   ap, b0l);
                MMA_BF16(o[2*np+1], ap, b1h);
                MMA_BF16(o[2*np+1], lp, b1h);
                MMA_BF16(o[2*np+1], ap, b1l);
            }
        }
        __syncthreads();
    }

    // ---- epilogue: x += O / l ----
    float i0 = 1.f / l0, i1 = 1.f / l1;
    long x0 = ((long)(b * S_ + qt * 128 + r0)) * D_ + h * HD_ + c2;
    long x1 = x0 + 8 * D_;
    #pragma unroll
    for (int nt = 0; nt < 16; ++nt) {
        float2 t0 = *(float2*)&x[x0 + nt * 8];
        t0.x += o[nt][0] * i0; t0.y += o[nt][1] * i0;
        *(float2*)&x[x0 + nt * 8] = t0;
        float2 t1 = *(float2*)&x[x1 + nt * 8];
        t1.x += o[nt][2] * i1; t1.y += o[nt][3] * i1;
        *(float2*)&x[x1 + nt * 8] = t1;
    }
}

// ================= elementwise kernels =================
__global__ void cvt_hilo4(const float4* __restrict__ x, uint2* __restrict__ hi,
                          uint2* __restrict__ lo, int n4) {
    int i = blockIdx.x * blockDim.x + threadIdx.x;
    if (i >= n4) return;
    float4 v = x[i];
    uint32_t h0, l0, h1, l1;
    packsplit(v.x, v.y, h0, l0);
    packsplit(v.z, v.w, h1, l1);
    hi[i] = make_uint2(h0, h1);
    lo[i] = make_uint2(l0, l1);
}

__global__ void pos_enc_kernel(const float* __restrict__ xin, const int* __restrict__ cpos,
                               float* __restrict__ xout) {
    int idx = blockIdx.x * blockDim.x + threadIdx.x;
    if (idx >= B_ * S_ * D_) return;
    int d = idx % D_;
    int s = (idx / D_) % S_;
    int i = d >> 1;
    float freq = expf(-(logf(10000.0f) / (float)D_) * (2.0f * (float)i));
    float ang  = (float)(cpos[0] + s) * freq;
    float pe   = (d & 1) ? cosf(ang) : sinf(ang);
    xout[idx] = xin[idx] + pe;
}

__global__ __launch_bounds__(256) void layernorm_kernel(
    const float* __restrict__ x, const float* __restrict__ w, const float* __restrict__ b,
    bf16* __restrict__ ohi, bf16* __restrict__ olo) {
    int row = blockIdx.x;
    const float* p = x + (long)row * D_;
    int tid = threadIdx.x;
    float vals[8];
    float sum = 0.f, sq = 0.f;
    #pragma unroll
    for (int k = 0; k < 8; ++k) {
        float v = p[tid + k * 256];
        vals[k] = v; sum += v; sq += v * v;
    }
    sum = warpSum(sum); sq = warpSum(sq);
    __shared__ float sh_s[8], sh_q[8];
    __shared__ float sh_mean, sh_inv;
    int wid = tid >> 5, lane = tid & 31;
    if (lane == 0) { sh_s[wid] = sum; sh_q[wid] = sq; }
    __syncthreads();
    if (tid == 0) {
        float ts = 0.f, tq = 0.f;
        #pragma unroll
        for (int k = 0; k < 8; ++k) { ts += sh_s[k]; tq += sh_q[k]; }
        float mean = ts / (float)D_;
        float var  = tq / (float)D_ - mean * mean;
        sh_mean = mean; sh_inv = rsqrtf(var + 1e-5f);
    }
    __syncthreads();
    float mean = sh_mean, inv = sh_inv;
    long base = (long)row * D_;
    #pragma unroll
    for (int k = 0; k < 8; ++k) {
        int c = tid + k * 256;
        float y = (vals[k] - mean) * inv * w[c] + b[c];
        split_store(y, &ohi[base + c], &olo[base + c]);
    }
}

// K gather, vectorized by 4 along d
__global__ void gather_k_kernel(const float* __restrict__ res, const float* __restrict__ off,
                                int layer, uint2* __restrict__ hi, uint2* __restrict__ lo) {
    int i4 = blockIdx.x * blockDim.x + threadIdx.x;
    if (i4 >= (B_ * H_ * KV2_ * HD_) / 4) return;
    int idx = i4 * 4;
    int d = idx % HD_;
    int j = (idx / HD_) % KV2_;
    int h = (idx / (HD_ * KV2_)) % H_;
    int b = idx / (HD_ * KV2_ * H_);
    float4 v;
    if (j < SKV_) {
        v = *(const float4*)&res[((((long)layer * B_ + b) * H_ + h) * SKV_ + j) * HD_ + d];
    } else {
        int j2 = j - SKV_;
        if (j2 == SKV_ - 1)
            v = *(const float4*)&g_qkv[(long)(b * S_ + (S_ - 1)) * D3_ + h * (3 * HD_) + HD_ + d];
        else
            v = *(const float4*)&off[((((long)layer * B_ + b) * H_ + h) * SKV_ + j2) * HD_ + d];
    }
    uint32_t h0, l0, h1, l1;
    packsplit(v.x, v.y, h0, l0);
    packsplit(v.z, v.w, h1, l1);
    hi[i4] = make_uint2(h0, h1);
    lo[i4] = make_uint2(l0, l1);
}

// V^T gather via smem tiled transpose
__global__ __launch_bounds__(256) void gather_vt_kernel(
    const float* __restrict__ res, const float* __restrict__ off, int layer,
    bf16* __restrict__ hi, bf16* __restrict__ lo) {
    __shared__ float t[32][33];
    const int jt = blockIdx.x * 32;
    const int dt = blockIdx.y * 32;
    const int bh = blockIdx.z;
    const int h = bh % H_, b = bh / H_;
    const int tx = threadIdx.x, ty = threadIdx.y;

    #pragma unroll
    for (int r = 0; r < 4; ++r) {
        int j = jt + ty + r * 8;
        int d = dt + tx;
        float v;
        if (j < SKV_) {
            v = res[((((long)layer * B_ + b) * H_ + h) * SKV_ + j) * HD_ + d];
        } else {
            int j2 = j - SKV_;
            if (j2 == SKV_ - 1)
                v = g_qkv[(long)(b * S_ + (S_ - 1)) * D3_ + h * (3 * HD_) + 2 * HD_ + d];
            else
                v = off[((((long)layer * B_ + b) * H_ + h) * SKV_ + j2) * HD_ + d];
        }
        t[ty + r * 8][tx] = v;
    }
    __syncthreads();
    #pragma unroll
    for (int r = 0; r < 4; ++r) {
        int d = dt + ty + r * 8;
        int j = jt + tx;
        long o = ((long)bh * HD_ + d) * KV2_ + j;
        split_store(t[tx][ty + r * 8], &hi[o], &lo[o]);
    }
}

__global__ __launch_bounds__(256) void softmax_rows(float* __restrict__ data, int width) {
    long row = blockIdx.x;
    float* p = data + row * (long)width;
    int tid = threadIdx.x;
    int wid = tid >> 5, lane = tid & 31;
    __shared__ float sh[8];
    __shared__ float sh_b;
    float m = -3.0e38f;
    for (int c = tid; c < width; c += 256) m = fmaxf(m, p[c]);
    m = warpMax(m);
    if (lane == 0) sh[wid] = m;
    __syncthreads();
    if (tid == 0) {
        float t = sh[0];
        #pragma unroll
        for (int k = 1; k < 8; ++k) t = fmaxf(t, sh[k]);
        sh_b = t;
    }
    __syncthreads();
    m = sh_b;
    float s = 0.f;
    for (int c = tid; c < width; c += 256) {
        float e = expf(p[c] - m);
        p[c] = e; s += e;
    }
    s = warpSum(s);
    if (lane == 0) sh[wid] = s;
    __syncthreads();
    if (tid == 0) {
        float t = 0.f;
        #pragma unroll
        for (int k = 0; k < 8; ++k) t += sh[k];
        sh_b = t;
    }
    __syncthreads();
    float inv = 1.0f / sh_b;
    for (int c = tid; c < width; c += 256) p[c] *= inv;
}

// ================= host orchestration =================
extern "C" void kernel_launch(void* const* d_in, const int* in_sizes, int n_in,
                              void* d_out, int out_size) {
    const float* x_in  = (const float*)d_in[0];
    const float* ln_w  = (const float*)d_in[1];
    const float* ln_b  = (const float*)d_in[2];
    const float* qkv_r = (const float*)d_in[3];
    const float* qkv_o = (const float*)d_in[4];
    const float* k_res = (const float*)d_in[5];
    const float* v_res = (const float*)d_in[6];
    const float* k_off = (const float*)d_in[7];
    const float* v_off = (const float*)d_in[8];
    const float* f1_r  = (const float*)d_in[9];
    const float* f1_o  = (const float*)d_in[10];
    const float* f2_r  = (const float*)d_in[11];
    const float* f2_o  = (const float*)d_in[12];
    const float* o_res = (const float*)d_in[13];
    const float* o_off = (const float*)d_in[14];
    const int*   cpos  = (const int*)d_in[15];
    float* out = (float*)d_out;

    #define GSA(p, sym) void* p##_v; cudaGetSymbolAddress(&p##_v, sym); auto p = (decltype(&sym[0]))p##_v
    GSA(px, g_x);       GSA(pqkv, g_qkv);
    GSA(xnh, g_xn_hi);  GSA(xnl, g_xn_lo);
    GSA(kh, g_k_hi);    GSA(kl, g_k_lo);
    GSA(vth, g_vt_hi);  GSA(vtl, g_vt_lo);
    GSA(hh, g_h_hi);    GSA(hl, g_h_lo);
    GSA(qrh, w_qr_hi);  GSA(qrl, w_qr_lo);  GSA(qoh, w_qo_hi);  GSA(qol, w_qo_lo);
    GSA(w1rh, w_1r_hi); GSA(w1rl, w_1r_lo); GSA(w1oh, w_1o_hi); GSA(w1ol, w_1o_lo);
    GSA(w2rh, w_2r_hi); GSA(w2rl, w_2r_lo); GSA(w2oh, w_2o_hi); GSA(w2ol, w_2o_lo);
    GSA(worh, w_or_hi); GSA(worl, w_or_lo); GSA(wooh, w_oo_hi); GSA(wool, w_oo_lo);
    #undef GSA

    cudaFuncSetAttribute(mm3<0>, cudaFuncAttributeMaxDynamicSharedMemorySize, MM_SMEM);
    cudaFuncSetAttribute(mm3<1>, cudaFuncAttributeMaxDynamicSharedMemorySize, MM_SMEM);
    cudaFuncSetAttribute(mm3<2>, cudaFuncAttributeMaxDynamicSharedMemorySize, MM_SMEM);
    cudaFuncSetAttribute(flash_attn, cudaFuncAttributeMaxDynamicSharedMemorySize, FA_SMEM);

    const int M = BS_;

    // weight conversion fp32 -> bf16 hi/lo (vectorized x4)
    #define CVT(src, dsth, dstl, n) \
        cvt_hilo4<<<((n) / 4 + 255) / 256, 256>>>((const float4*)(src), (uint2*)(dsth), (uint2*)(dstl), (n) / 4)
    const int nQ = L_ * (D3_ / 2) * D_;
    const int n1 = L_ * (D4_ / 2) * D_;
    const int n2 = L_ * (D_ / 2) * D4_;
    const int nO = (V_ / 2) * D_;
    CVT(qkv_r, qrh, qrl, nQ);
    CVT(qkv_o, qoh, qol, nQ);
    CVT(f1_r, w1rh, w1rl, n1);
    CVT(f1_o, w1oh, w1ol, n1);
    CVT(f2_r, w2rh, w2rl, n2);
    CVT(f2_o, w2oh, w2ol, n2);
    CVT(o_res, worh, worl, nO);
    CVT(o_off, wooh, wool, nO);
    #undef CVT

    pos_enc_kernel<<<(B_ * S_ * D_ + 255) / 256, 256>>>(x_in, cpos, px);

    for (int i = 0; i < L_; ++i) {
        const long oq = (long)i * (D3_ / 2) * D_;
        const long o1 = (long)i * (D4_ / 2) * D_;
        const long o2 = (long)i * (D_ / 2) * D4_;

        // ---- attention ----
        layernorm_kernel<<<M, 256>>>(px, ln_w, ln_b, xnh, xnl);

        mm3<0><<<dim3(D3_ / 128, M / 128, 1), 256, MM_SMEM>>>(
            xnh, xnl, 0, D_, qrh + oq, qrl + oq, qoh + oq, qol + oq, D3_ / 2, 0, D_,
            pqkv, (bf16*)0, (bf16*)0, 0, 0, 1, D3_, D_, 1.0f);

        gather_k_kernel<<<(B_ * H_ * KV2_ * HD_ / 4 + 255) / 256, 256>>>(k_res, k_off, i, (uint2*)kh, (uint2*)kl);
        gather_vt_kernel<<<dim3(KV2_ / 32, HD_ / 32, B_ * H_), dim3(32, 8)>>>(v_res, v_off, i, vth, vtl);

        // fused flash attention: x += softmax(scale * Q K^T) V
        flash_attn<<<dim3(S_ / 128, B_ * H_), 256, FA_SMEM>>>(kh, kl, vth, vtl, px);

        // ---- FFN ----
        layernorm_kernel<<<M, 256>>>(px, ln_w, ln_b, xnh, xnl);

        mm3<1><<<dim3(D4_ / 128, M / 128, 1), 256, MM_SMEM>>>(
            xnh, xnl, 0, D_, w1rh + o1, w1rl + o1, w1oh + o1, w1ol + o1, D4_ / 2, 0, D_,
            (float*)0, hh, hl, 0, 0, 1, D4_, D_, 1.0f);

        mm3<2><<<dim3(D_ / 128, M / 128, 1), 256, MM_SMEM>>>(
            hh, hl, 0, D4_, w2rh + o2, w2rl + o2, w2oh + o2, w2ol + o2, D_ / 2, 0, D4_,
            px, (bf16*)0, (bf16*)0, 0, 0, 1, D_, D4_, 1.0f);
    }

    layernorm_kernel<<<M, 256>>>(px, ln_w, ln_b, xnh, xnl);
    mm3<0><<<dim3(V_ / 128, M / 128, 1), 256, MM_SMEM>>>(
        xnh, xnl, 0, D_, worh, worl, wooh, wool, V_ / 2, 0, D_,
        out, (bf16*)0, (bf16*)0, 0, 0, 1, V_, D_, 1.0f);
    softmax_rows<<<M, 256>>>(out, V_);
}